// round 8
// baseline (speedup 1.0000x reference)
#include <cuda_runtime.h>
#include <cuda_fp16.h>
#include <math.h>

#define BB 32
#define LL 196
#define DM 512
#define DI 256
#define M_TOK (BB*LL)   // 6272

// ------------------------ scratch ------------------------
__device__ __align__(16) float  g_t[M_TOK*DM];
__device__ __align__(16) float  g_xz[M_TOK*2*DI];
__device__ __align__(16) float  g_xm[M_TOK*DI];
__device__ __align__(16) float  g_dbc[M_TOK*384];
__device__ __align__(16) float  g_tmean[BB*DM];
__device__ __align__(16) float  g_pooled[BB*1024];
__device__ __align__(16) __half g_patches_h[M_TOK*768];
__device__ __align__(16) __half g_h_h[M_TOK*DM];
__device__ __align__(16) __half g_xm_h[M_TOK*DI];
__device__ __align__(16) __half g_cat_h[M_TOK*2*DI];
__device__ __align__(16) __half g_qkv_h[M_TOK*3*DM];
__device__ __align__(16) __half g_o_h[M_TOK*DM];
__device__ __align__(16) __half g_hid_h[M_TOK*2048];
__device__ __align__(16) __half g_wpool_h[4161536];

// weight pool offsets (elements)
#define WOFF_PATCH 0
#define WOFF_INP   393216
#define WOFF_OUTP  655360
#define WOFF_QKV   917504
#define WOFF_ATTNP 1703936
#define WOFF_MLP1  1966080
#define WOFF_MLP2  3014656
#define WOFF_COMB  4063232   // 384x256 combined dt/B/C projection

// ------------------------ fused weight fp32 -> fp16 (all 7 big weights) ---------
__global__ void cvtall_kernel(const float* __restrict__ pw,  const float* __restrict__ ipw,
                              const float* __restrict__ opw, const float* __restrict__ qw,
                              const float* __restrict__ apw, const float* __restrict__ m1,
                              const float* __restrict__ m2,  __half* __restrict__ dst){
    int i = blockIdx.x*blockDim.x + threadIdx.x;
    if (i >= 1015808) return;
    const float* src; int base;
    if      (i <  98304){ src=pw;  base=0; }
    else if (i < 163840){ src=ipw; base=98304; }
    else if (i < 229376){ src=opw; base=163840; }
    else if (i < 425984){ src=qw;  base=229376; }
    else if (i < 491520){ src=apw; base=425984; }
    else if (i < 753664){ src=m1;  base=491520; }
    else                { src=m2;  base=753664; }
    float4 v = ((const float4*)src)[i-base];
    __half2 h0 = __floats2half2_rn(v.x, v.y);
    __half2 h1 = __floats2half2_rn(v.z, v.w);
    ((uint2*)dst)[i] = make_uint2(*(unsigned*)&h0, *(unsigned*)&h1);
}

// ------------------------ combined dt/B/C weight build ------------------------
// comb[384,256] fp16: rows 0..255  = dt_proj_w @ x_proj_w[0:16]  (W_dt)
//                     rows 256..287 = x_proj_w rows 16..47 (B then C)
//                     rows 288..383 = 0
__global__ void wdt_kernel(const float* __restrict__ dtw, const float* __restrict__ xpw,
                           __half* __restrict__ comb){
    int idx = blockIdx.x*blockDim.x + threadIdx.x;   // 384*256 = 98304
    if (idx >= 98304) return;
    int n = idx >> 8, k = idx & 255;
    float v = 0.f;
    if (n < 256){
        #pragma unroll
        for (int j=0;j<16;j++) v += dtw[n*16+j]*xpw[j*256+k];
    } else if (n < 288){
        v = xpw[(n-240)*256 + k];   // n-256+16
    }
    comb[idx] = __float2half_rn(v);
}

// ------------------------ im2col for patch conv (half out) ------------------------
__global__ void im2col_kernel(const float* __restrict__ x, __half* __restrict__ out){
    int idx = blockIdx.x*blockDim.x + threadIdx.x;
    if (idx >= M_TOK*768) return;
    int m = idx / 768, k = idx % 768;
    int b = m / LL, l = m % LL;
    int py = l / 14, px = l % 14;
    int c = k / 256, r = k % 256;
    int i = r / 16, j = r % 16;
    out[idx] = __float2half_rn(x[(((size_t)b*3 + c)*224 + py*16 + i)*224 + px*16 + j]);
}

// ------------------------ FP16 tensor-core GEMM ------------------------
// C[M,N] = A[M,K] @ W[N,K]^T (+bias)(+act)(+res). A, W fp16, accum fp32.
// REQUIRES M%128==0, N%128==0, K%32==0.
// act: 0 none, 1 softplus on cols<256 (bias also only cols<256), 2 gelu.
__device__ __forceinline__ void ldm4(unsigned* r, const __half* p){
    unsigned addr = (unsigned)__cvta_generic_to_shared(p);
    asm volatile("ldmatrix.sync.aligned.m8n8.x4.shared.b16 {%0,%1,%2,%3}, [%4];"
        : "=r"(r[0]), "=r"(r[1]), "=r"(r[2]), "=r"(r[3]) : "r"(addr));
}
#define HMMA(cacc, a, b0, b1) \
    asm volatile("mma.sync.aligned.m16n8k16.row.col.f32.f16.f16.f32 " \
        "{%0,%1,%2,%3}, {%4,%5,%6,%7}, {%8,%9}, {%0,%1,%2,%3};" \
        : "+f"(cacc[0]), "+f"(cacc[1]), "+f"(cacc[2]), "+f"(cacc[3]) \
        : "r"(a[0]), "r"(a[1]), "r"(a[2]), "r"(a[3]), "r"(b0), "r"(b1))

__global__ void __launch_bounds__(256,2) hgemm_kernel(
        const __half* __restrict__ A, int lda,
        const __half* __restrict__ W,
        const float* __restrict__ bias,
        const float* __restrict__ res, int ldres,
        float* __restrict__ C, __half* __restrict__ Ch, int ldc,
        int M, int N, int K, int act)
{
    __shared__ __align__(16) __half sA[2][128*40];
    __shared__ __align__(16) __half sW[2][128*40];
    int bm = blockIdx.y*128, bn = blockIdx.x*128;
    int tid = threadIdx.x;
    int warp = tid >> 5, lane = tid & 31;
    int wm = (warp >> 1) * 32;
    int wn = (warp & 1) * 64;
    int gid = lane >> 2, tig = lane & 3;
    int lane15 = lane & 15, laneh = lane >> 4;

    float c[2][8][4];
    #pragma unroll
    for (int mi=0;mi<2;mi++)
        #pragma unroll
        for (int ni=0;ni<8;ni++)
            #pragma unroll
            for (int q=0;q<4;q++) c[mi][ni][q] = 0.f;

    int srow = tid >> 1;
    int skb  = (tid & 1) * 16;
    const __half* Ag = A + (size_t)(bm+srow)*lda + skb;
    const __half* Wg = W + (size_t)(bn+srow)*K   + skb;
    uint4 pa0, pa1, pw0, pw1;

    #define LDCHUNK(k0) { \
        pa0 = *(const uint4*)(Ag + (k0));      pa1 = *(const uint4*)(Ag + (k0) + 8); \
        pw0 = *(const uint4*)(Wg + (k0));      pw1 = *(const uint4*)(Wg + (k0) + 8); }
    #define STCHUNK(bf) { \
        *(uint4*)&sA[bf][srow*40 + skb]     = pa0; \
        *(uint4*)&sA[bf][srow*40 + skb + 8] = pa1; \
        *(uint4*)&sW[bf][srow*40 + skb]     = pw0; \
        *(uint4*)&sW[bf][srow*40 + skb + 8] = pw1; }

    const int niter = K >> 5;
    LDCHUNK(0);
    STCHUNK(0);

    for (int i=0; i<niter; i++){
        if (i+1 < niter) LDCHUNK((i+1)*32);
        __syncthreads();
        const __half* sAb = sA[i & 1];
        const __half* sWb = sW[i & 1];
        #pragma unroll
        for (int kh=0; kh<2; kh++){
            unsigned a[2][4];
            #pragma unroll
            for (int mi=0;mi<2;mi++)
                ldm4(a[mi], sAb + (wm + mi*16 + lane15)*40 + kh*16 + laneh*8);
            #pragma unroll
            for (int nip=0; nip<4; nip++){
                unsigned bf[4];
                ldm4(bf, sWb + (wn + nip*16 + lane15)*40 + kh*16 + laneh*8);
                #pragma unroll
                for (int mi=0;mi<2;mi++){
                    HMMA(c[mi][2*nip],   a[mi], bf[0], bf[2]);
                    HMMA(c[mi][2*nip+1], a[mi], bf[1], bf[3]);
                }
            }
        }
        if (i+1 < niter) STCHUNK((i+1) & 1);
    }

    // epilogue
    #pragma unroll
    for (int mi=0;mi<2;mi++){
        #pragma unroll
        for (int ni=0;ni<8;ni++){
            int col = bn + wn + ni*8 + 2*tig;
            #pragma unroll
            for (int half=0; half<2; half++){
                int row = bm + wm + mi*16 + gid + half*8;
                float v0 = c[mi][ni][half*2+0];
                float v1 = c[mi][ni][half*2+1];
                if (bias && (act != 1 || col < 256)){ v0 += bias[col]; v1 += bias[col+1]; }
                if (act == 2){
                    float u = v0, t = tanhf(0.7978845608f*(u + 0.044715f*u*u*u));
                    v0 = 0.5f*u*(1.f + t);
                    u = v1; t = tanhf(0.7978845608f*(u + 0.044715f*u*u*u));
                    v1 = 0.5f*u*(1.f + t);
                } else if (act == 1 && col < 256){
                    v0 = (v0 > 20.f) ? v0 : log1pf(expf(v0));
                    v1 = (v1 > 20.f) ? v1 : log1pf(expf(v1));
                }
                if (res){
                    v0 += res[(size_t)row*ldres + col];
                    v1 += res[(size_t)row*ldres + col+1];
                }
                if (C)  *(float2*)&C[(size_t)row*ldc + col] = make_float2(v0, v1);
                if (Ch) *(__half2*)&Ch[(size_t)row*ldc + col] = __floats2half2_rn(v0, v1);
            }
        }
    }
}

// ------------------------ scalar SGEMM (head: M=32) ------------------------
__global__ void sgemm_kernel(const float* __restrict__ A, int lda,
                             const float* __restrict__ W,
                             const float* __restrict__ bias,
                             float* __restrict__ C, int ldc,
                             int M, int N, int K)
{
    __shared__ float As[16][65];
    __shared__ float Bs[16][65];
    int bm = blockIdx.y*64, bn = blockIdx.x*64;
    int tx = threadIdx.x & 15, ty = threadIdx.x >> 4;
    float acc[4][4];
    #pragma unroll
    for (int i=0;i<4;i++)
        #pragma unroll
        for (int j=0;j<4;j++) acc[i][j]=0.f;

    int lm = threadIdx.x >> 2;
    int lq = (threadIdx.x & 3) * 4;
    int arow = bm + lm;
    int wrow = bn + lm;

    for (int k0=0;k0<K;k0+=16){
        float4 av = make_float4(0.f,0.f,0.f,0.f);
        float4 wv = make_float4(0.f,0.f,0.f,0.f);
        if (arow < M) av = *(const float4*)&A[(size_t)arow*lda + k0 + lq];
        if (wrow < N) wv = *(const float4*)&W[(size_t)wrow*K   + k0 + lq];
        As[lq+0][lm]=av.x; As[lq+1][lm]=av.y; As[lq+2][lm]=av.z; As[lq+3][lm]=av.w;
        Bs[lq+0][lm]=wv.x; Bs[lq+1][lm]=wv.y; Bs[lq+2][lm]=wv.z; Bs[lq+3][lm]=wv.w;
        __syncthreads();
        #pragma unroll
        for (int kk=0;kk<16;kk++){
            float a[4], bv[4];
            #pragma unroll
            for (int i=0;i<4;i++) a[i] = As[kk][ty + 16*i];
            #pragma unroll
            for (int j=0;j<4;j++) bv[j] = Bs[kk][tx + 16*j];
            #pragma unroll
            for (int i=0;i<4;i++)
                #pragma unroll
                for (int j=0;j<4;j++) acc[i][j] += a[i]*bv[j];
        }
        __syncthreads();
    }
    #pragma unroll
    for (int i=0;i<4;i++){
        int row = bm + ty + 16*i;
        if (row >= M) continue;
        #pragma unroll
        for (int j=0;j<4;j++){
            int col = bn + tx + 16*j;
            if (col >= N) continue;
            float v = acc[i][j];
            if (bias) v += bias[col];
            C[(size_t)row*ldc + col] = v;
        }
    }
}

// ------------------------ LayerNorm (half out) ------------------------
__global__ void ln_kernel(const float* __restrict__ x, const float* __restrict__ g,
                          const float* __restrict__ be, __half* __restrict__ y){
    int m = blockIdx.x;
    const float* row = x + (size_t)m*DM;
    float s = 0.f, ss = 0.f;
    for (int c = threadIdx.x; c < DM; c += 256){ float v = row[c]; s += v; ss += v*v; }
    #pragma unroll
    for (int off=16;off;off>>=1){ s += __shfl_xor_sync(~0u,s,off); ss += __shfl_xor_sync(~0u,ss,off); }
    __shared__ float sh[16];
    __shared__ float stat[2];
    int wid = threadIdx.x >> 5, lid = threadIdx.x & 31;
    if (lid == 0){ sh[wid] = s; sh[wid+8] = ss; }
    __syncthreads();
    if (threadIdx.x == 0){
        float ts=0.f, tss=0.f;
        for (int w=0;w<8;w++){ ts += sh[w]; tss += sh[w+8]; }
        float mean = ts * (1.f/DM);
        float var  = tss * (1.f/DM) - mean*mean;
        stat[0] = mean;
        stat[1] = rsqrtf(var + 1e-6f);
    }
    __syncthreads();
    float mean = stat[0], rstd = stat[1];
    for (int c = threadIdx.x; c < DM; c += 256){
        y[(size_t)m*DM + c] = __float2half_rn((row[c] - mean)*rstd*g[c] + be[c]);
    }
}

// ------------------------ causal depthwise conv (k=4) + SiLU ------------------------
__global__ void conv_silu_kernel(const float* __restrict__ xz,
                                 const float* __restrict__ wx, const float* __restrict__ bx,
                                 const float* __restrict__ wz, const float* __restrict__ bz,
                                 float* __restrict__ xm, __half* __restrict__ xm_h,
                                 __half* __restrict__ cat){
    int idx = blockIdx.x*blockDim.x + threadIdx.x;
    if (idx >= M_TOK*512) return;
    int m = idx >> 9, c = idx & 511;
    int b = m / LL, l = m % LL;
    bool isx = (c < 256);
    int ci = isx ? c : c - 256;
    const float* w = isx ? (wx + ci*4) : (wz + ci*4);
    float s = isx ? bx[ci] : bz[ci];
    #pragma unroll
    for (int k=0;k<4;k++){
        int ls = l - 3 + k;
        if (ls >= 0) s += w[k] * xz[((size_t)(b*LL + ls))*512 + c];
    }
    float v = s / (1.f + expf(-s));   // silu
    if (isx){
        xm[(size_t)m*256 + ci] = v;
        xm_h[(size_t)m*256 + ci] = __float2half_rn(v);
    } else {
        cat[(size_t)m*512 + c] = __float2half_rn(v);
    }
}

// ------------------------ selective scan ------------------------
// dbc layout per token: [0..255] dt (softplus'd), [256..271] B, [272..287] C
__global__ void scan_kernel(const float* __restrict__ dbc,
                            const float* __restrict__ xm, const float* __restrict__ A_log,
                            const float* __restrict__ Dp, __half* __restrict__ cat){
    int gid = blockIdx.x*blockDim.x + threadIdx.x;
    int pair = gid >> 4, n = gid & 15;
    int b = pair >> 8, d = pair & 255;
    float A = -expf(A_log[d*16 + n]);
    float Dval = Dp[d];
    float hst = 0.f;
    int base = b*LL;
    for (int l=0;l<LL;l++){
        int m = base + l;
        float dtv = dbc[(size_t)m*384 + d];
        float u   = xm[(size_t)m*256 + d];
        float Bv  = dbc[(size_t)m*384 + 256 + n];
        float Cv  = dbc[(size_t)m*384 + 272 + n];
        hst = expf(dtv*A)*hst + (dtv*u)*Bv;
        float y = hst*Cv;
        #pragma unroll
        for (int off=8;off;off>>=1) y += __shfl_xor_sync(~0u, y, off);
        if (n == 0) cat[(size_t)m*512 + d] = __float2half_rn(y + Dval*u);
    }
}

// ------------------------ attention (flash-style, float4-vectorized smem) ---------
__global__ void __launch_bounds__(224) attn_kernel(const __half* __restrict__ qkv, __half* __restrict__ o){
    extern __shared__ float smem[];
    float* Ks = smem;
    float* Vs = smem + LL*64;
    int bh = blockIdx.x; int b = bh >> 3, h = bh & 7;
    for (int idx = threadIdx.x; idx < LL*64; idx += 224){
        int l = idx >> 6, dd = idx & 63;
        const __half* p = qkv + (size_t)(b*LL + l)*1536 + h*64 + dd;
        Ks[idx] = __half2float(p[512]);
        Vs[idx] = __half2float(p[1024]);
    }
    __syncthreads();
    int l = threadIdx.x;
    if (l < LL){
        float4 q4[16];
        {
            const __half* qp = qkv + (size_t)(b*LL + l)*1536 + h*64;
            #pragma unroll
            for (int i=0;i<16;i++){
                q4[i] = make_float4(__half2float(qp[4*i]),   __half2float(qp[4*i+1]),
                                    __half2float(qp[4*i+2]), __half2float(qp[4*i+3]));
            }
        }
        float4 oa[16];
        #pragma unroll
        for (int i=0;i<16;i++) oa[i] = make_float4(0.f,0.f,0.f,0.f);
        float m = -1e30f, ssum = 0.f;
        for (int jb=0; jb<LL; jb+=14){
            float s[14];
            float mx = m;
            #pragma unroll
            for (int jj=0;jj<14;jj++){
                const float4* kp = (const float4*)(Ks + (jb+jj)*64);
                float acc = 0.f;
                #pragma unroll
                for (int i=0;i<16;i++){
                    float4 kv = kp[i];
                    acc += q4[i].x*kv.x + q4[i].y*kv.y + q4[i].z*kv.z + q4[i].w*kv.w;
                }
                acc *= 0.125f;
                s[jj] = acc;
                mx = fmaxf(mx, acc);
            }
            float scale = expf(m - mx);
            ssum *= scale;
            #pragma unroll
            for (int i=0;i<16;i++){
                oa[i].x *= scale; oa[i].y *= scale; oa[i].z *= scale; oa[i].w *= scale;
            }
            m = mx;
            #pragma unroll
            for (int jj=0;jj<14;jj++){
                float e = expf(s[jj] - m);
                ssum += e;
                const float4* vp = (const float4*)(Vs + (jb+jj)*64);
                #pragma unroll
                for (int i=0;i<16;i++){
                    float4 vv = vp[i];
                    oa[i].x += e*vv.x; oa[i].y += e*vv.y; oa[i].z += e*vv.z; oa[i].w += e*vv.w;
                }
            }
        }
        float inv = 1.f/ssum;
        __half* op = o + (size_t)(b*LL + l)*512 + h*64;
        #pragma unroll
        for (int i=0;i<16;i++){
            op[4*i]   = __float2half_rn(oa[i].x*inv);
            op[4*i+1] = __float2half_rn(oa[i].y*inv);
            op[4*i+2] = __float2half_rn(oa[i].z*inv);
            op[4*i+3] = __float2half_rn(oa[i].w*inv);
        }
    }
}

// ------------------------ mean over L ------------------------
__global__ void pool_kernel(const float* __restrict__ t, float* __restrict__ tmean){
    int idx = blockIdx.x*blockDim.x + threadIdx.x;
    if (idx >= BB*DM) return;
    int b = idx / DM, c = idx % DM;
    const float* p = t + (size_t)b*LL*DM + c;
    float s = 0.f;
    for (int l=0;l<LL;l++) s += p[(size_t)l*DM];
    tmean[idx] = s * (1.f/LL);
}

// ------------------------ final fc ------------------------
__global__ void fc_kernel(const float* __restrict__ pooled, const float* __restrict__ fw,
                          const float* __restrict__ fb, float* __restrict__ out){
    int i = threadIdx.x; // 0..127
    int b = i >> 2, oi = i & 3;
    float s = fb[oi];
    const float* pp = pooled + b*1024;
    const float* wp = fw + oi*1024;
    for (int k=0;k<1024;k++) s += pp[k]*wp[k];
    out[b*4 + oi] = s;
}

// ------------------------ host ------------------------
static void hgemm(const __half* A, int lda, const __half* W, const float* bias,
                  const float* res, int ldres, float* C, __half* Ch, int ldc,
                  int M, int N, int K, int act){
    dim3 grid(N/128, M/128);
    hgemm_kernel<<<grid, 256>>>(A, lda, W, bias, res, ldres, C, Ch, ldc, M, N, K, act);
}

extern "C" void kernel_launch(void* const* d_in, const int* in_sizes, int n_in,
                              void* d_out, int out_size)
{
    const float* x          = (const float*)d_in[0];
    const float* patch_w    = (const float*)d_in[1];
    const float* patch_b    = (const float*)d_in[2];
    const float* ln1_g      = (const float*)d_in[3];
    const float* ln1_b      = (const float*)d_in[4];
    const float* in_proj_w  = (const float*)d_in[5];
    const float* convx_w    = (const float*)d_in[6];
    const float* convx_b    = (const float*)d_in[7];
    const float* convz_w    = (const float*)d_in[8];
    const float* convz_b    = (const float*)d_in[9];
    const float* x_proj_w   = (const float*)d_in[10];
    const float* dt_proj_w  = (const float*)d_in[11];
    const float* dt_proj_b  = (const float*)d_in[12];
    const float* A_log      = (const float*)d_in[13];
    const float* Dp         = (const float*)d_in[14];
    const float* out_proj_w = (const float*)d_in[15];
    const float* ln2_g      = (const float*)d_in[16];
    const float* ln2_b      = (const float*)d_in[17];
    const float* qkv_w      = (const float*)d_in[18];
    const float* attn_proj_w= (const float*)d_in[19];
    const float* ln3_g      = (const float*)d_in[20];
    const float* ln3_b      = (const float*)d_in[21];
    const float* mlp_w1     = (const float*)d_in[22];
    const float* mlp_b1     = (const float*)d_in[23];
    const float* mlp_w2     = (const float*)d_in[24];
    const float* mlp_b2     = (const float*)d_in[25];
    const float* head_w     = (const float*)d_in[26];
    const float* head_b     = (const float*)d_in[27];
    const float* fc_w       = (const float*)d_in[28];
    const float* fc_b       = (const float*)d_in[29];
    float* out = (float*)d_out;

    float *t,*xz,*xm,*dbc,*tmean,*pooled;
    __half *patches,*h,*xm_h,*cat,*qkv,*o,*hid,*wpool;
    cudaGetSymbolAddress((void**)&t,       g_t);
    cudaGetSymbolAddress((void**)&xz,      g_xz);
    cudaGetSymbolAddress((void**)&xm,      g_xm);
    cudaGetSymbolAddress((void**)&dbc,     g_dbc);
    cudaGetSymbolAddress((void**)&tmean,   g_tmean);
    cudaGetSymbolAddress((void**)&pooled,  g_pooled);
    cudaGetSymbolAddress((void**)&patches, g_patches_h);
    cudaGetSymbolAddress((void**)&h,       g_h_h);
    cudaGetSymbolAddress((void**)&xm_h,    g_xm_h);
    cudaGetSymbolAddress((void**)&cat,     g_cat_h);
    cudaGetSymbolAddress((void**)&qkv,     g_qkv_h);
    cudaGetSymbolAddress((void**)&o,       g_o_h);
    cudaGetSymbolAddress((void**)&hid,     g_hid_h);
    cudaGetSymbolAddress((void**)&wpool,   g_wpool_h);

    cudaFuncSetAttribute(attn_kernel, cudaFuncAttributeMaxDynamicSharedMemorySize, 2*LL*64*4);

    // 0. weights -> fp16 pool (one launch) + combined dt/B/C weight
    cvtall_kernel<<<(1015808+255)/256,256>>>(patch_w, in_proj_w, out_proj_w, qkv_w,
                                             attn_proj_w, mlp_w1, mlp_w2, wpool);
    wdt_kernel<<<(98304+255)/256,256>>>(dt_proj_w, x_proj_w, wpool+WOFF_COMB);

    // 1. patch embed
    im2col_kernel<<<(M_TOK*768 + 255)/256, 256>>>(x, patches);
    hgemm(patches, 768, wpool+WOFF_PATCH, patch_b, nullptr, 0, t, nullptr, 512, M_TOK, 512, 768, 0);
    // 2. mamba branch
    ln_kernel<<<M_TOK, 256>>>(t, ln1_g, ln1_b, h);
    hgemm(h, 512, wpool+WOFF_INP, nullptr, nullptr, 0, xz, nullptr, 512, M_TOK, 512, 512, 0);
    conv_silu_kernel<<<(M_TOK*512 + 255)/256, 256>>>(xz, convx_w, convx_b, convz_w, convz_b, xm, xm_h, cat);
    hgemm(xm_h, 256, wpool+WOFF_COMB, dt_proj_b, nullptr, 0, dbc, nullptr, 384, M_TOK, 384, 256, 1);
    scan_kernel<<<512, 256>>>(dbc, xm, A_log, Dp, cat);
    hgemm(cat, 512, wpool+WOFF_OUTP, nullptr, t, 512, t, nullptr, 512, M_TOK, 512, 512, 0);
    // 3. attention
    ln_kernel<<<M_TOK, 256>>>(t, ln2_g, ln2_b, h);
    hgemm(h, 512, wpool+WOFF_QKV, nullptr, nullptr, 0, nullptr, qkv, 1536, M_TOK, 1536, 512, 0);
    attn_kernel<<<BB*8, 224, 2*LL*64*4>>>(qkv, o);
    hgemm(o, 512, wpool+WOFF_ATTNP, nullptr, t, 512, t, nullptr, 512, M_TOK, 512, 512, 0);
    // 4. MLP
    ln_kernel<<<M_TOK, 256>>>(t, ln3_g, ln3_b, h);
    hgemm(h, 512, wpool+WOFF_MLP1, mlp_b1, nullptr, 0, nullptr, hid, 2048, M_TOK, 2048, 512, 2);
    hgemm(hid, 2048, wpool+WOFF_MLP2, mlp_b2, t, 512, t, nullptr, 512, M_TOK, 512, 2048, 0);
    // 5. head (pool first: mean_L(t @ W^T + b) == mean_L(t) @ W^T + b)
    pool_kernel<<<(BB*DM + 255)/256, 256>>>(t, tmean);
    {
        dim3 grid((1024+63)/64, 1);
        sgemm_kernel<<<grid, 256>>>(tmean, 512, head_w, head_b, pooled, 1024, BB, 1024, 512);
    }
    fc_kernel<<<1, 128>>>(pooled, fc_w, fc_b, out);
}

// round 11
// speedup vs baseline: 1.0232x; 1.0232x over previous
#include <cuda_runtime.h>
#include <cuda_fp16.h>
#include <math.h>

#define BB 32
#define LL 196
#define DM 512
#define DI 256
#define M_TOK (BB*LL)   // 6272

// ------------------------ scratch ------------------------
__device__ __align__(16) float  g_t[M_TOK*DM];
__device__ __align__(16) float  g_xz[M_TOK*2*DI];
__device__ __align__(16) float  g_xm[M_TOK*DI];
__device__ __align__(16) float  g_dbc[M_TOK*384];
__device__ __align__(16) float  g_tmean[BB*DM];
__device__ __align__(16) float  g_pooled[BB*1024];
__device__ __align__(16) __half g_patches_h[M_TOK*768];
__device__ __align__(16) __half g_h_h[M_TOK*DM];
__device__ __align__(16) __half g_xm_h[M_TOK*DI];
__device__ __align__(16) __half g_cat_h[M_TOK*2*DI];
__device__ __align__(16) __half g_qkv_h[M_TOK*3*DM];
__device__ __align__(16) __half g_o_h[M_TOK*DM];
__device__ __align__(16) __half g_hid_h[M_TOK*2048];
__device__ __align__(16) __half g_wpool_h[4161536];

// weight pool offsets (elements)
#define WOFF_PATCH 0
#define WOFF_INP   393216
#define WOFF_OUTP  655360
#define WOFF_QKV   917504
#define WOFF_ATTNP 1703936
#define WOFF_MLP1  1966080
#define WOFF_MLP2  3014656
#define WOFF_COMB  4063232   // 384x256 combined dt/B/C projection

// ------------------------ fused weight fp32 -> fp16 (all 7 big weights) ---------
__global__ void cvtall_kernel(const float* __restrict__ pw,  const float* __restrict__ ipw,
                              const float* __restrict__ opw, const float* __restrict__ qw,
                              const float* __restrict__ apw, const float* __restrict__ m1,
                              const float* __restrict__ m2,  __half* __restrict__ dst){
    int i = blockIdx.x*blockDim.x + threadIdx.x;
    if (i >= 1015808) return;
    const float* src; int base;
    if      (i <  98304){ src=pw;  base=0; }
    else if (i < 163840){ src=ipw; base=98304; }
    else if (i < 229376){ src=opw; base=163840; }
    else if (i < 425984){ src=qw;  base=229376; }
    else if (i < 491520){ src=apw; base=425984; }
    else if (i < 753664){ src=m1;  base=491520; }
    else                { src=m2;  base=753664; }
    float4 v = ((const float4*)src)[i-base];
    __half2 h0 = __floats2half2_rn(v.x, v.y);
    __half2 h1 = __floats2half2_rn(v.z, v.w);
    ((uint2*)dst)[i] = make_uint2(*(unsigned*)&h0, *(unsigned*)&h1);
}

// ------------------------ combined dt/B/C weight build ------------------------
__global__ void wdt_kernel(const float* __restrict__ dtw, const float* __restrict__ xpw,
                           __half* __restrict__ comb){
    int idx = blockIdx.x*blockDim.x + threadIdx.x;   // 384*256 = 98304
    if (idx >= 98304) return;
    int n = idx >> 8, k = idx & 255;
    float v = 0.f;
    if (n < 256){
        #pragma unroll
        for (int j=0;j<16;j++) v += dtw[n*16+j]*xpw[j*256+k];
    } else if (n < 288){
        v = xpw[(n-240)*256 + k];
    }
    comb[idx] = __float2half_rn(v);
}

// ------------------------ im2col (half out) ------------------------
__global__ void im2col_kernel(const float* __restrict__ x, __half* __restrict__ out){
    int idx = blockIdx.x*blockDim.x + threadIdx.x;
    if (idx >= M_TOK*768) return;
    int m = idx / 768, k = idx % 768;
    int b = m / LL, l = m % LL;
    int py = l / 14, px = l % 14;
    int c = k / 256, r = k % 256;
    int i = r / 16, j = r % 16;
    out[idx] = __float2half_rn(x[(((size_t)b*3 + c)*224 + py*16 + i)*224 + px*16 + j]);
}

// ------------------------ FP16 tensor-core GEMM (512 thr, 16 warps) ------------
// C[M,N] = A[M,K] @ W[N,K]^T (+bias)(+act)(+res). A, W fp16, accum fp32.
// REQUIRES M%128==0, N%128==0, K%32==0.
// act: 0 none, 1 softplus cols<256 (bias only cols<256), 2 gelu.
// Block 128x128, 16 warps (4m x 4n), warp tile 32x32, mma m16n8k16, ldmatrix.x4,
// double-buffered smem (rows padded to 40 halfs = 80B -> conflict-free LDSM).
__device__ __forceinline__ void ldm4(unsigned* r, const __half* p){
    unsigned addr = (unsigned)__cvta_generic_to_shared(p);
    asm volatile("ldmatrix.sync.aligned.m8n8.x4.shared.b16 {%0,%1,%2,%3}, [%4];"
        : "=r"(r[0]), "=r"(r[1]), "=r"(r[2]), "=r"(r[3]) : "r"(addr));
}
#define HMMA(cacc, a, b0, b1) \
    asm volatile("mma.sync.aligned.m16n8k16.row.col.f32.f16.f16.f32 " \
        "{%0,%1,%2,%3}, {%4,%5,%6,%7}, {%8,%9}, {%0,%1,%2,%3};" \
        : "+f"(cacc[0]), "+f"(cacc[1]), "+f"(cacc[2]), "+f"(cacc[3]) \
        : "r"(a[0]), "r"(a[1]), "r"(a[2]), "r"(a[3]), "r"(b0), "r"(b1))

__global__ void __launch_bounds__(512,2) hgemm_kernel(
        const __half* __restrict__ A, int lda,
        const __half* __restrict__ W,
        const float* __restrict__ bias,
        const float* __restrict__ res, int ldres,
        float* __restrict__ C, __half* __restrict__ Ch, int ldc,
        int M, int N, int K, int act)
{
    __shared__ __align__(16) __half sA[2][128*40];
    __shared__ __align__(16) __half sW[2][128*40];
    int bm = blockIdx.y*128, bn = blockIdx.x*128;
    int tid = threadIdx.x;
    int warp = tid >> 5, lane = tid & 31;
    int wm = (warp & 3) * 32;
    int wn = (warp >> 2) * 32;
    int gid = lane >> 2, tig = lane & 3;
    int lane15 = lane & 15, laneh = lane >> 4;

    float c[2][4][4];
    #pragma unroll
    for (int mi=0;mi<2;mi++)
        #pragma unroll
        for (int ni=0;ni<4;ni++)
            #pragma unroll
            for (int q=0;q<4;q++) c[mi][ni][q] = 0.f;

    // staging: one uint4 per thread per operand: row = tid>>2, kb = (tid&3)*8
    int srow = tid >> 2;
    int skb  = (tid & 3) * 8;
    const __half* Ag = A + (size_t)(bm+srow)*lda + skb;
    const __half* Wg = W + (size_t)(bn+srow)*K   + skb;
    uint4 pa, pw;

    #define LDCHUNK(k0) { \
        pa = *(const uint4*)(Ag + (k0)); \
        pw = *(const uint4*)(Wg + (k0)); }
    #define STCHUNK(bf) { \
        *(uint4*)&sA[bf][srow*40 + skb] = pa; \
        *(uint4*)&sW[bf][srow*40 + skb] = pw; }

    const int niter = K >> 5;
    LDCHUNK(0);
    STCHUNK(0);

    for (int i=0; i<niter; i++){
        if (i+1 < niter) LDCHUNK((i+1)*32);
        __syncthreads();
        const __half* sAb = sA[i & 1];
        const __half* sWb = sW[i & 1];
        #pragma unroll
        for (int kh=0; kh<2; kh++){
            unsigned a[2][4], bf[2][4];
            #pragma unroll
            for (int mi=0;mi<2;mi++)
                ldm4(a[mi], sAb + (wm + mi*16 + lane15)*40 + kh*16 + laneh*8);
            #pragma unroll
            for (int nip=0; nip<2; nip++)
                ldm4(bf[nip], sWb + (wn + nip*16 + lane15)*40 + kh*16 + laneh*8);
            #pragma unroll
            for (int mi=0;mi<2;mi++)
                #pragma unroll
                for (int nip=0; nip<2; nip++){
                    HMMA(c[mi][2*nip],   a[mi], bf[nip][0], bf[nip][2]);
                    HMMA(c[mi][2*nip+1], a[mi], bf[nip][1], bf[nip][3]);
                }
        }
        if (i+1 < niter) STCHUNK((i+1) & 1);
    }

    // epilogue
    #pragma unroll
    for (int mi=0;mi<2;mi++){
        #pragma unroll
        for (int ni=0;ni<4;ni++){
            int col = bn + wn + ni*8 + 2*tig;
            #pragma unroll
            for (int half=0; half<2; half++){
                int row = bm + wm + mi*16 + gid + half*8;
                float v0 = c[mi][ni][half*2+0];
                float v1 = c[mi][ni][half*2+1];
                if (bias && (act != 1 || col < 256)){ v0 += bias[col]; v1 += bias[col+1]; }
                if (act == 2){
                    float u = v0, t = tanhf(0.7978845608f*(u + 0.044715f*u*u*u));
                    v0 = 0.5f*u*(1.f + t);
                    u = v1; t = tanhf(0.7978845608f*(u + 0.044715f*u*u*u));
                    v1 = 0.5f*u*(1.f + t);
                } else if (act == 1 && col < 256){
                    v0 = (v0 > 20.f) ? v0 : log1pf(expf(v0));
                    v1 = (v1 > 20.f) ? v1 : log1pf(expf(v1));
                }
                if (res){
                    v0 += res[(size_t)row*ldres + col];
                    v1 += res[(size_t)row*ldres + col+1];
                }
                if (C)  *(float2*)&C[(size_t)row*ldc + col] = make_float2(v0, v1);
                if (Ch) *(__half2*)&Ch[(size_t)row*ldc + col] = __floats2half2_rn(v0, v1);
            }
        }
    }
}

// ------------------------ scalar SGEMM (head: M=32) ------------------------
__global__ void sgemm_kernel(const float* __restrict__ A, int lda,
                             const float* __restrict__ W,
                             const float* __restrict__ bias,
                             float* __restrict__ C, int ldc,
                             int M, int N, int K)
{
    __shared__ float As[16][65];
    __shared__ float Bs[16][65];
    int bm = blockIdx.y*64, bn = blockIdx.x*64;
    int tx = threadIdx.x & 15, ty = threadIdx.x >> 4;
    float acc[4][4];
    #pragma unroll
    for (int i=0;i<4;i++)
        #pragma unroll
        for (int j=0;j<4;j++) acc[i][j]=0.f;

    int lm = threadIdx.x >> 2;
    int lq = (threadIdx.x & 3) * 4;
    int arow = bm + lm;
    int wrow = bn + lm;

    for (int k0=0;k0<K;k0+=16){
        float4 av = make_float4(0.f,0.f,0.f,0.f);
        float4 wv = make_float4(0.f,0.f,0.f,0.f);
        if (arow < M) av = *(const float4*)&A[(size_t)arow*lda + k0 + lq];
        if (wrow < N) wv = *(const float4*)&W[(size_t)wrow*K   + k0 + lq];
        As[lq+0][lm]=av.x; As[lq+1][lm]=av.y; As[lq+2][lm]=av.z; As[lq+3][lm]=av.w;
        Bs[lq+0][lm]=wv.x; Bs[lq+1][lm]=wv.y; Bs[lq+2][lm]=wv.z; Bs[lq+3][lm]=wv.w;
        __syncthreads();
        #pragma unroll
        for (int kk=0;kk<16;kk++){
            float a[4], bv[4];
            #pragma unroll
            for (int i=0;i<4;i++) a[i] = As[kk][ty + 16*i];
            #pragma unroll
            for (int j=0;j<4;j++) bv[j] = Bs[kk][tx + 16*j];
            #pragma unroll
            for (int i=0;i<4;i++)
                #pragma unroll
                for (int j=0;j<4;j++) acc[i][j] += a[i]*bv[j];
        }
        __syncthreads();
    }
    #pragma unroll
    for (int i=0;i<4;i++){
        int row = bm + ty + 16*i;
        if (row >= M) continue;
        #pragma unroll
        for (int j=0;j<4;j++){
            int col = bn + tx + 16*j;
            if (col >= N) continue;
            float v = acc[i][j];
            if (bias) v += bias[col];
            C[(size_t)row*ldc + col] = v;
        }
    }
}

// ------------------------ LayerNorm (half out) ------------------------
__global__ void ln_kernel(const float* __restrict__ x, const float* __restrict__ g,
                          const float* __restrict__ be, __half* __restrict__ y){
    int m = blockIdx.x;
    const float* row = x + (size_t)m*DM;
    float s = 0.f, ss = 0.f;
    for (int c = threadIdx.x; c < DM; c += 256){ float v = row[c]; s += v; ss += v*v; }
    #pragma unroll
    for (int off=16;off;off>>=1){ s += __shfl_xor_sync(~0u,s,off); ss += __shfl_xor_sync(~0u,ss,off); }
    __shared__ float sh[16];
    __shared__ float stat[2];
    int wid = threadIdx.x >> 5, lid = threadIdx.x & 31;
    if (lid == 0){ sh[wid] = s; sh[wid+8] = ss; }
    __syncthreads();
    if (threadIdx.x == 0){
        float ts=0.f, tss=0.f;
        for (int w=0;w<8;w++){ ts += sh[w]; tss += sh[w+8]; }
        float mean = ts * (1.f/DM);
        float var  = tss * (1.f/DM) - mean*mean;
        stat[0] = mean;
        stat[1] = rsqrtf(var + 1e-6f);
    }
    __syncthreads();
    float mean = stat[0], rstd = stat[1];
    for (int c = threadIdx.x; c < DM; c += 256){
        y[(size_t)m*DM + c] = __float2half_rn((row[c] - mean)*rstd*g[c] + be[c]);
    }
}

// ------------------------ causal depthwise conv (k=4) + SiLU ------------------------
__global__ void conv_silu_kernel(const float* __restrict__ xz,
                                 const float* __restrict__ wx, const float* __restrict__ bx,
                                 const float* __restrict__ wz, const float* __restrict__ bz,
                                 float* __restrict__ xm, __half* __restrict__ xm_h,
                                 __half* __restrict__ cat){
    int idx = blockIdx.x*blockDim.x + threadIdx.x;
    if (idx >= M_TOK*512) return;
    int m = idx >> 9, c = idx & 511;
    int b = m / LL, l = m % LL;
    bool isx = (c < 256);
    int ci = isx ? c : c - 256;
    const float* w = isx ? (wx + ci*4) : (wz + ci*4);
    float s = isx ? bx[ci] : bz[ci];
    #pragma unroll
    for (int k=0;k<4;k++){
        int ls = l - 3 + k;
        if (ls >= 0) s += w[k] * xz[((size_t)(b*LL + ls))*512 + c];
    }
    float v = s / (1.f + expf(-s));   // silu
    if (isx){
        xm[(size_t)m*256 + ci] = v;
        xm_h[(size_t)m*256 + ci] = __float2half_rn(v);
    } else {
        cat[(size_t)m*512 + c] = __float2half_rn(v);
    }
}

// ------------------------ selective scan ------------------------
// dbc layout per token: [0..255] dt (softplus'd), [256..271] B, [272..287] C
__global__ void scan_kernel(const float* __restrict__ dbc,
                            const float* __restrict__ xm, const float* __restrict__ A_log,
                            const float* __restrict__ Dp, __half* __restrict__ cat){
    int gid = blockIdx.x*blockDim.x + threadIdx.x;
    int pair = gid >> 4, n = gid & 15;
    int b = pair >> 8, d = pair & 255;
    float A = -expf(A_log[d*16 + n]);
    float Dval = Dp[d];
    float hst = 0.f;
    int base = b*LL;
    for (int l=0;l<LL;l++){
        int m = base + l;
        float dtv = dbc[(size_t)m*384 + d];
        float u   = xm[(size_t)m*256 + d];
        float Bv  = dbc[(size_t)m*384 + 256 + n];
        float Cv  = dbc[(size_t)m*384 + 272 + n];
        hst = expf(dtv*A)*hst + (dtv*u)*Bv;
        float y = hst*Cv;
        #pragma unroll
        for (int off=8;off;off>>=1) y += __shfl_xor_sync(~0u, y, off);
        if (n == 0) cat[(size_t)m*512 + d] = __float2half_rn(y + Dval*u);
    }
}

// ------------------------ attention (flash-style, float4-vectorized smem) ---------
__global__ void __launch_bounds__(224) attn_kernel(const __half* __restrict__ qkv, __half* __restrict__ o){
    extern __shared__ float smem[];
    float* Ks = smem;
    float* Vs = smem + LL*64;
    int bh = blockIdx.x; int b = bh >> 3, h = bh & 7;
    for (int idx = threadIdx.x; idx < LL*64; idx += 224){
        int l = idx >> 6, dd = idx & 63;
        const __half* p = qkv + (size_t)(b*LL + l)*1536 + h*64 + dd;
        Ks[idx] = __half2float(p[512]);
        Vs[idx] = __half2float(p[1024]);
    }
    __syncthreads();
    int l = threadIdx.x;
    if (l < LL){
        float4 q4[16];
        {
            const __half* qp = qkv + (size_t)(b*LL + l)*1536 + h*64;
            #pragma unroll
            for (int i=0;i<16;i++){
                q4[i] = make_float4(__half2float(qp[4*i]),   __half2float(qp[4*i+1]),
                                    __half2float(qp[4*i+2]), __half2float(qp[4*i+3]));
            }
        }
        float4 oa[16];
        #pragma unroll
        for (int i=0;i<16;i++) oa[i] = make_float4(0.f,0.f,0.f,0.f);
        float m = -1e30f, ssum = 0.f;
        for (int jb=0; jb<LL; jb+=14){
            float s[14];
            float mx = m;
            #pragma unroll
            for (int jj=0;jj<14;jj++){
                const float4* kp = (const float4*)(Ks + (jb+jj)*64);
                float acc = 0.f;
                #pragma unroll
                for (int i=0;i<16;i++){
                    float4 kv = kp[i];
                    acc += q4[i].x*kv.x + q4[i].y*kv.y + q4[i].z*kv.z + q4[i].w*kv.w;
                }
                acc *= 0.125f;
                s[jj] = acc;
                mx = fmaxf(mx, acc);
            }
            float scale = expf(m - mx);
            ssum *= scale;
            #pragma unroll
            for (int i=0;i<16;i++){
                oa[i].x *= scale; oa[i].y *= scale; oa[i].z *= scale; oa[i].w *= scale;
            }
            m = mx;
            #pragma unroll
            for (int jj=0;jj<14;jj++){
                float e = expf(s[jj] - m);
                ssum += e;
                const float4* vp = (const float4*)(Vs + (jb+jj)*64);
                #pragma unroll
                for (int i=0;i<16;i++){
                    float4 vv = vp[i];
                    oa[i].x += e*vv.x; oa[i].y += e*vv.y; oa[i].z += e*vv.z; oa[i].w += e*vv.w;
                }
            }
        }
        float inv = 1.f/ssum;
        __half* op = o + (size_t)(b*LL + l)*512 + h*64;
        #pragma unroll
        for (int i=0;i<16;i++){
            op[4*i]   = __float2half_rn(oa[i].x*inv);
            op[4*i+1] = __float2half_rn(oa[i].y*inv);
            op[4*i+2] = __float2half_rn(oa[i].z*inv);
            op[4*i+3] = __float2half_rn(oa[i].w*inv);
        }
    }
}

// ------------------------ mean over L ------------------------
__global__ void pool_kernel(const float* __restrict__ t, float* __restrict__ tmean){
    int idx = blockIdx.x*blockDim.x + threadIdx.x;
    if (idx >= BB*DM) return;
    int b = idx / DM, c = idx % DM;
    const float* p = t + (size_t)b*LL*DM + c;
    float s = 0.f;
    for (int l=0;l<LL;l++) s += p[(size_t)l*DM];
    tmean[idx] = s * (1.f/LL);
}

// ------------------------ final fc ------------------------
__global__ void fc_kernel(const float* __restrict__ pooled, const float* __restrict__ fw,
                          const float* __restrict__ fb, float* __restrict__ out){
    int i = threadIdx.x; // 0..127
    int b = i >> 2, oi = i & 3;
    float s = fb[oi];
    const float* pp = pooled + b*1024;
    const float* wp = fw + oi*1024;
    for (int k=0;k<1024;k++) s += pp[k]*wp[k];
    out[b*4 + oi] = s;
}

// ------------------------ host ------------------------
static void hgemm(const __half* A, int lda, const __half* W, const float* bias,
                  const float* res, int ldres, float* C, __half* Ch, int ldc,
                  int M, int N, int K, int act){
    dim3 grid(N/128, M/128);
    hgemm_kernel<<<grid, 512>>>(A, lda, W, bias, res, ldres, C, Ch, ldc, M, N, K, act);
}

extern "C" void kernel_launch(void* const* d_in, const int* in_sizes, int n_in,
                              void* d_out, int out_size)
{
    const float* x          = (const float*)d_in[0];
    const float* patch_w    = (const float*)d_in[1];
    const float* patch_b    = (const float*)d_in[2];
    const float* ln1_g      = (const float*)d_in[3];
    const float* ln1_b      = (const float*)d_in[4];
    const float* in_proj_w  = (const float*)d_in[5];
    const float* convx_w    = (const float*)d_in[6];
    const float* convx_b    = (const float*)d_in[7];
    const float* convz_w    = (const float*)d_in[8];
    const float* convz_b    = (const float*)d_in[9];
    const float* x_proj_w   = (const float*)d_in[10];
    const float* dt_proj_w  = (const float*)d_in[11];
    const float* dt_proj_b  = (const float*)d_in[12];
    const float* A_log      = (const float*)d_in[13];
    const float* Dp         = (const float*)d_in[14];
    const float* out_proj_w = (const float*)d_in[15];
    const float* ln2_g      = (const float*)d_in[16];
    const float* ln2_b      = (const float*)d_in[17];
    const float* qkv_w      = (const float*)d_in[18];
    const float* attn_proj_w= (const float*)d_in[19];
    const float* ln3_g      = (const float*)d_in[20];
    const float* ln3_b      = (const float*)d_in[21];
    const float* mlp_w1     = (const float*)d_in[22];
    const float* mlp_b1     = (const float*)d_in[23];
    const float* mlp_w2     = (const float*)d_in[24];
    const float* mlp_b2     = (const float*)d_in[25];
    const float* head_w     = (const float*)d_in[26];
    const float* head_b     = (const float*)d_in[27];
    const float* fc_w       = (const float*)d_in[28];
    const float* fc_b       = (const float*)d_in[29];
    float* out = (float*)d_out;

    float *t,*xz,*xm,*dbc,*tmean,*pooled;
    __half *patches,*h,*xm_h,*cat,*qkv,*o,*hid,*wpool;
    cudaGetSymbolAddress((void**)&t,       g_t);
    cudaGetSymbolAddress((void**)&xz,      g_xz);
    cudaGetSymbolAddress((void**)&xm,      g_xm);
    cudaGetSymbolAddress((void**)&dbc,     g_dbc);
    cudaGetSymbolAddress((void**)&tmean,   g_tmean);
    cudaGetSymbolAddress((void**)&pooled,  g_pooled);
    cudaGetSymbolAddress((void**)&patches, g_patches_h);
    cudaGetSymbolAddress((void**)&h,       g_h_h);
    cudaGetSymbolAddress((void**)&xm_h,    g_xm_h);
    cudaGetSymbolAddress((void**)&cat,     g_cat_h);
    cudaGetSymbolAddress((void**)&qkv,     g_qkv_h);
    cudaGetSymbolAddress((void**)&o,       g_o_h);
    cudaGetSymbolAddress((void**)&hid,     g_hid_h);
    cudaGetSymbolAddress((void**)&wpool,   g_wpool_h);

    cudaFuncSetAttribute(attn_kernel, cudaFuncAttributeMaxDynamicSharedMemorySize, 2*LL*64*4);

    // 0. weights -> fp16 pool (one launch) + combined dt/B/C weight
    cvtall_kernel<<<(1015808+255)/256,256>>>(patch_w, in_proj_w, out_proj_w, qkv_w,
                                             attn_proj_w, mlp_w1, mlp_w2, wpool);
    wdt_kernel<<<(98304+255)/256,256>>>(dt_proj_w, x_proj_w, wpool+WOFF_COMB);

    // 1. patch embed
    im2col_kernel<<<(M_TOK*768 + 255)/256, 256>>>(x, patches);
    hgemm(patches, 768, wpool+WOFF_PATCH, patch_b, nullptr, 0, t, nullptr, 512, M_TOK, 512, 768, 0);
    // 2. mamba branch
    ln_kernel<<<M_TOK, 256>>>(t, ln1_g, ln1_b, h);
    hgemm(h, 512, wpool+WOFF_INP, nullptr, nullptr, 0, xz, nullptr, 512, M_TOK, 512, 512, 0);
    conv_silu_kernel<<<(M_TOK*512 + 255)/256, 256>>>(xz, convx_w, convx_b, convz_w, convz_b, xm, xm_h, cat);
    hgemm(xm_h, 256, wpool+WOFF_COMB, dt_proj_b, nullptr, 0, dbc, nullptr, 384, M_TOK, 384, 256, 1);
    scan_kernel<<<512, 256>>>(dbc, xm, A_log, Dp, cat);
    hgemm(cat, 512, wpool+WOFF_OUTP, nullptr, t, 512, t, nullptr, 512, M_TOK, 512, 512, 0);
    // 3. attention
    ln_kernel<<<M_TOK, 256>>>(t, ln2_g, ln2_b, h);
    hgemm(h, 512, wpool+WOFF_QKV, nullptr, nullptr, 0, nullptr, qkv, 1536, M_TOK, 1536, 512, 0);
    attn_kernel<<<BB*8, 224, 2*LL*64*4>>>(qkv, o);
    hgemm(o, 512, wpool+WOFF_ATTNP, nullptr, t, 512, t, nullptr, 512, M_TOK, 512, 512, 0);
    // 4. MLP
    ln_kernel<<<M_TOK, 256>>>(t, ln3_g, ln3_b, h);
    hgemm(h, 512, wpool+WOFF_MLP1, mlp_b1, nullptr, 0, nullptr, hid, 2048, M_TOK, 2048, 512, 2);
    hgemm(hid, 2048, wpool+WOFF_MLP2, mlp_b2, t, 512, t, nullptr, 512, M_TOK, 512, 2048, 0);
    // 5. head (pool first: mean_L(t @ W^T + b) == mean_L(t) @ W^T + b)
    pool_kernel<<<(BB*DM + 255)/256, 256>>>(t, tmean);
    {
        dim3 grid((1024+63)/64, 1);
        sgemm_kernel<<<grid, 256>>>(tmean, 512, head_w, head_b, pooled, 1024, BB, 1024, 512);
    }
    fc_kernel<<<1, 128>>>(pooled, fc_w, fc_b, out);
}

// round 12
// speedup vs baseline: 1.0398x; 1.0162x over previous
#include <cuda_runtime.h>
#include <cuda_fp16.h>
#include <math.h>

#define BB 32
#define LL 196
#define DM 512
#define DI 256
#define M_TOK (BB*LL)   // 6272

// ------------------------ scratch ------------------------
__device__ __align__(16) float  g_t[M_TOK*DM];
__device__ __align__(16) float  g_xz[M_TOK*2*DI];
__device__ __align__(16) float  g_xm[M_TOK*DI];
__device__ __align__(16) float  g_dbc[M_TOK*384];
__device__ __align__(16) float  g_tmean[BB*DM];
__device__ __align__(16) float  g_pooled[BB*1024];
__device__ __align__(16) __half g_patches_h[M_TOK*768];
__device__ __align__(16) __half g_h_h[M_TOK*DM];
__device__ __align__(16) __half g_xm_h[M_TOK*DI];
__device__ __align__(16) __half g_cat_h[M_TOK*2*DI];
__device__ __align__(16) __half g_qkv_h[M_TOK*3*DM];
__device__ __align__(16) __half g_o_h[M_TOK*DM];
__device__ __align__(16) __half g_hid_h[M_TOK*2048];
__device__ __align__(16) __half g_wpool_h[4161536];

// weight pool offsets (elements)
#define WOFF_PATCH 0
#define WOFF_INP   393216
#define WOFF_OUTP  655360
#define WOFF_QKV   917504
#define WOFF_ATTNP 1703936
#define WOFF_MLP1  1966080
#define WOFF_MLP2  3014656
#define WOFF_COMB  4063232   // 384x256 combined dt/B/C projection

// ------------------------ fused weight fp32 -> fp16 (all 7 big weights) ---------
__global__ void cvtall_kernel(const float* __restrict__ pw,  const float* __restrict__ ipw,
                              const float* __restrict__ opw, const float* __restrict__ qw,
                              const float* __restrict__ apw, const float* __restrict__ m1,
                              const float* __restrict__ m2,  __half* __restrict__ dst){
    int i = blockIdx.x*blockDim.x + threadIdx.x;
    if (i >= 1015808) return;
    const float* src; int base;
    if      (i <  98304){ src=pw;  base=0; }
    else if (i < 163840){ src=ipw; base=98304; }
    else if (i < 229376){ src=opw; base=163840; }
    else if (i < 425984){ src=qw;  base=229376; }
    else if (i < 491520){ src=apw; base=425984; }
    else if (i < 753664){ src=m1;  base=491520; }
    else                { src=m2;  base=753664; }
    float4 v = ((const float4*)src)[i-base];
    __half2 h0 = __floats2half2_rn(v.x, v.y);
    __half2 h1 = __floats2half2_rn(v.z, v.w);
    ((uint2*)dst)[i] = make_uint2(*(unsigned*)&h0, *(unsigned*)&h1);
}

// ------------------------ combined dt/B/C weight build ------------------------
__global__ void wdt_kernel(const float* __restrict__ dtw, const float* __restrict__ xpw,
                           __half* __restrict__ comb){
    int idx = blockIdx.x*blockDim.x + threadIdx.x;   // 384*256 = 98304
    if (idx >= 98304) return;
    int n = idx >> 8, k = idx & 255;
    float v = 0.f;
    if (n < 256){
        #pragma unroll
        for (int j=0;j<16;j++) v += dtw[n*16+j]*xpw[j*256+k];
    } else if (n < 288){
        v = xpw[(n-240)*256 + k];
    }
    comb[idx] = __float2half_rn(v);
}

// ------------------------ im2col (half out) ------------------------
__global__ void im2col_kernel(const float* __restrict__ x, __half* __restrict__ out){
    int idx = blockIdx.x*blockDim.x + threadIdx.x;
    if (idx >= M_TOK*768) return;
    int m = idx / 768, k = idx % 768;
    int b = m / LL, l = m % LL;
    int py = l / 14, px = l % 14;
    int c = k / 256, r = k % 256;
    int i = r / 16, j = r % 16;
    out[idx] = __float2half_rn(x[(((size_t)b*3 + c)*224 + py*16 + i)*224 + px*16 + j]);
}

// ------------------------ FP16 tensor-core GEMM (512 thr, 16 warps) ------------
// C[M,N] = A[M,K] @ W[N,K]^T (+bias)(+act)(+res). A, W fp16, accum fp32.
// REQUIRES M%128==0, N%128==0, K%64==0 (niter even).
// act: 0 none, 1 softplus cols<256 (bias only cols<256), 2 gelu.
// Block 128x128, 16 warps (4m x 4n), warp tile 32x32, mma m16n8k16, ldmatrix.x4,
// double-buffered smem, rows padded to 40 halfs (80B), precomputed LDSM addrs.
__device__ __forceinline__ void ldm4a(unsigned* r, unsigned addr){
    asm volatile("ldmatrix.sync.aligned.m8n8.x4.shared.b16 {%0,%1,%2,%3}, [%4];"
        : "=r"(r[0]), "=r"(r[1]), "=r"(r[2]), "=r"(r[3]) : "r"(addr));
}
#define HMMA(cacc, a, b0, b1) \
    asm volatile("mma.sync.aligned.m16n8k16.row.col.f32.f16.f16.f32 " \
        "{%0,%1,%2,%3}, {%4,%5,%6,%7}, {%8,%9}, {%0,%1,%2,%3};" \
        : "+f"(cacc[0]), "+f"(cacc[1]), "+f"(cacc[2]), "+f"(cacc[3]) \
        : "r"(a[0]), "r"(a[1]), "r"(a[2]), "r"(a[3]), "r"(b0), "r"(b1))

#define BUFSTRIDE 10240u   // 128*40 halfs * 2B

__global__ void __launch_bounds__(512,2) hgemm_kernel(
        const __half* __restrict__ A, int lda,
        const __half* __restrict__ W,
        const float* __restrict__ bias,
        const float* __restrict__ res, int ldres,
        float* __restrict__ C, __half* __restrict__ Ch, int ldc,
        int M, int N, int K, int act)
{
    __shared__ __align__(16) __half sA[2][128*40];
    __shared__ __align__(16) __half sW[2][128*40];
    int bm = blockIdx.y*128, bn = blockIdx.x*128;
    int tid = threadIdx.x;
    int warp = tid >> 5, lane = tid & 31;
    int wm = (warp & 3) * 32;
    int wn = (warp >> 2) * 32;
    int gid = lane >> 2, tig = lane & 3;
    int lane15 = lane & 15, laneh = lane >> 4;

    float c[2][4][4];
    #pragma unroll
    for (int mi=0;mi<2;mi++)
        #pragma unroll
        for (int ni=0;ni<4;ni++)
            #pragma unroll
            for (int q=0;q<4;q++) c[mi][ni][q] = 0.f;

    // precomputed LDSM fragment base addresses (shared space, buffer 0)
    unsigned sAbase = (unsigned)__cvta_generic_to_shared(&sA[0][0]);
    unsigned sWbase = (unsigned)__cvta_generic_to_shared(&sW[0][0]);
    unsigned aAddr[2], wAddr[2];
    #pragma unroll
    for (int mi=0;mi<2;mi++)
        aAddr[mi] = sAbase + (unsigned)(((wm + mi*16 + lane15)*40 + laneh*8) * 2);
    #pragma unroll
    for (int nip=0;nip<2;nip++)
        wAddr[nip] = sWbase + (unsigned)(((wn + nip*16 + lane15)*40 + laneh*8) * 2);

    // staging: one uint4 per thread per operand: row = tid>>2, kb = (tid&3)*8
    int srow = tid >> 2;
    int skb  = (tid & 3) * 8;
    const __half* Ag = A + (size_t)(bm+srow)*lda + skb;
    const __half* Wg = W + (size_t)(bn+srow)*K   + skb;
    uint4 pa, pw;

    #define LDCHUNK(k0) { \
        pa = *(const uint4*)(Ag + (k0)); \
        pw = *(const uint4*)(Wg + (k0)); }
    #define STCHUNK(bf) { \
        *(uint4*)&sA[bf][srow*40 + skb] = pa; \
        *(uint4*)&sW[bf][srow*40 + skb] = pw; }

    // compute one 32-K chunk from buffer with byte offset boff (0 or BUFSTRIDE)
    #define COMPUTE(boff) { \
        _Pragma("unroll") \
        for (int kh=0; kh<2; kh++){ \
            unsigned a[2][4], bf[2][4]; \
            ldm4a(a[0],  aAddr[0] + (boff) + kh*32); \
            ldm4a(a[1],  aAddr[1] + (boff) + kh*32); \
            ldm4a(bf[0], wAddr[0] + (boff) + kh*32); \
            ldm4a(bf[1], wAddr[1] + (boff) + kh*32); \
            _Pragma("unroll") \
            for (int mi=0;mi<2;mi++) \
                _Pragma("unroll") \
                for (int nip=0; nip<2; nip++){ \
                    HMMA(c[mi][2*nip],   a[mi], bf[nip][0], bf[nip][2]); \
                    HMMA(c[mi][2*nip+1], a[mi], bf[nip][1], bf[nip][3]); \
                } \
        } }

    const int niter = K >> 5;   // even for all shapes used
    LDCHUNK(0);
    STCHUNK(0);

    for (int i=0; i<niter; i+=2){
        // chunk i (buffer 0)
        LDCHUNK((i+1)*32);
        __syncthreads();
        COMPUTE(0u);
        STCHUNK(1);
        // chunk i+1 (buffer 1)
        if (i+2 < niter) LDCHUNK((i+2)*32);
        __syncthreads();
        COMPUTE(BUFSTRIDE);
        if (i+2 < niter) STCHUNK(0);
    }

    // epilogue
    #pragma unroll
    for (int mi=0;mi<2;mi++){
        #pragma unroll
        for (int ni=0;ni<4;ni++){
            int col = bn + wn + ni*8 + 2*tig;
            #pragma unroll
            for (int half=0; half<2; half++){
                int row = bm + wm + mi*16 + gid + half*8;
                float v0 = c[mi][ni][half*2+0];
                float v1 = c[mi][ni][half*2+1];
                if (bias && (act != 1 || col < 256)){ v0 += bias[col]; v1 += bias[col+1]; }
                if (act == 2){
                    float u = v0, t = tanhf(0.7978845608f*(u + 0.044715f*u*u*u));
                    v0 = 0.5f*u*(1.f + t);
                    u = v1; t = tanhf(0.7978845608f*(u + 0.044715f*u*u*u));
                    v1 = 0.5f*u*(1.f + t);
                } else if (act == 1 && col < 256){
                    v0 = (v0 > 20.f) ? v0 : log1pf(expf(v0));
                    v1 = (v1 > 20.f) ? v1 : log1pf(expf(v1));
                }
                if (res){
                    v0 += res[(size_t)row*ldres + col];
                    v1 += res[(size_t)row*ldres + col+1];
                }
                if (C)  *(float2*)&C[(size_t)row*ldc + col] = make_float2(v0, v1);
                if (Ch) *(__half2*)&Ch[(size_t)row*ldc + col] = __floats2half2_rn(v0, v1);
            }
        }
    }
}

// ------------------------ scalar SGEMM (head: M=32) ------------------------
__global__ void sgemm_kernel(const float* __restrict__ A, int lda,
                             const float* __restrict__ W,
                             const float* __restrict__ bias,
                             float* __restrict__ C, int ldc,
                             int M, int N, int K)
{
    __shared__ float As[16][65];
    __shared__ float Bs[16][65];
    int bm = blockIdx.y*64, bn = blockIdx.x*64;
    int tx = threadIdx.x & 15, ty = threadIdx.x >> 4;
    float acc[4][4];
    #pragma unroll
    for (int i=0;i<4;i++)
        #pragma unroll
        for (int j=0;j<4;j++) acc[i][j]=0.f;

    int lm = threadIdx.x >> 2;
    int lq = (threadIdx.x & 3) * 4;
    int arow = bm + lm;
    int wrow = bn + lm;

    for (int k0=0;k0<K;k0+=16){
        float4 av = make_float4(0.f,0.f,0.f,0.f);
        float4 wv = make_float4(0.f,0.f,0.f,0.f);
        if (arow < M) av = *(const float4*)&A[(size_t)arow*lda + k0 + lq];
        if (wrow < N) wv = *(const float4*)&W[(size_t)wrow*K   + k0 + lq];
        As[lq+0][lm]=av.x; As[lq+1][lm]=av.y; As[lq+2][lm]=av.z; As[lq+3][lm]=av.w;
        Bs[lq+0][lm]=wv.x; Bs[lq+1][lm]=wv.y; Bs[lq+2][lm]=wv.z; Bs[lq+3][lm]=wv.w;
        __syncthreads();
        #pragma unroll
        for (int kk=0;kk<16;kk++){
            float a[4], bv[4];
            #pragma unroll
            for (int i=0;i<4;i++) a[i] = As[kk][ty + 16*i];
            #pragma unroll
            for (int j=0;j<4;j++) bv[j] = Bs[kk][tx + 16*j];
            #pragma unroll
            for (int i=0;i<4;i++)
                #pragma unroll
                for (int j=0;j<4;j++) acc[i][j] += a[i]*bv[j];
        }
        __syncthreads();
    }
    #pragma unroll
    for (int i=0;i<4;i++){
        int row = bm + ty + 16*i;
        if (row >= M) continue;
        #pragma unroll
        for (int j=0;j<4;j++){
            int col = bn + tx + 16*j;
            if (col >= N) continue;
            float v = acc[i][j];
            if (bias) v += bias[col];
            C[(size_t)row*ldc + col] = v;
        }
    }
}

// ------------------------ LayerNorm (half out) ------------------------
__global__ void ln_kernel(const float* __restrict__ x, const float* __restrict__ g,
                          const float* __restrict__ be, __half* __restrict__ y){
    int m = blockIdx.x;
    const float* row = x + (size_t)m*DM;
    float s = 0.f, ss = 0.f;
    for (int c = threadIdx.x; c < DM; c += 256){ float v = row[c]; s += v; ss += v*v; }
    #pragma unroll
    for (int off=16;off;off>>=1){ s += __shfl_xor_sync(~0u,s,off); ss += __shfl_xor_sync(~0u,ss,off); }
    __shared__ float sh[16];
    __shared__ float stat[2];
    int wid = threadIdx.x >> 5, lid = threadIdx.x & 31;
    if (lid == 0){ sh[wid] = s; sh[wid+8] = ss; }
    __syncthreads();
    if (threadIdx.x == 0){
        float ts=0.f, tss=0.f;
        for (int w=0;w<8;w++){ ts += sh[w]; tss += sh[w+8]; }
        float mean = ts * (1.f/DM);
        float var  = tss * (1.f/DM) - mean*mean;
        stat[0] = mean;
        stat[1] = rsqrtf(var + 1e-6f);
    }
    __syncthreads();
    float mean = stat[0], rstd = stat[1];
    for (int c = threadIdx.x; c < DM; c += 256){
        y[(size_t)m*DM + c] = __float2half_rn((row[c] - mean)*rstd*g[c] + be[c]);
    }
}

// ------------------------ causal depthwise conv (k=4) + SiLU ------------------------
__global__ void conv_silu_kernel(const float* __restrict__ xz,
                                 const float* __restrict__ wx, const float* __restrict__ bx,
                                 const float* __restrict__ wz, const float* __restrict__ bz,
                                 float* __restrict__ xm, __half* __restrict__ xm_h,
                                 __half* __restrict__ cat){
    int idx = blockIdx.x*blockDim.x + threadIdx.x;
    if (idx >= M_TOK*512) return;
    int m = idx >> 9, c = idx & 511;
    int b = m / LL, l = m % LL;
    bool isx = (c < 256);
    int ci = isx ? c : c - 256;
    const float* w = isx ? (wx + ci*4) : (wz + ci*4);
    float s = isx ? bx[ci] : bz[ci];
    #pragma unroll
    for (int k=0;k<4;k++){
        int ls = l - 3 + k;
        if (ls >= 0) s += w[k] * xz[((size_t)(b*LL + ls))*512 + c];
    }
    float v = s / (1.f + expf(-s));   // silu
    if (isx){
        xm[(size_t)m*256 + ci] = v;
        xm_h[(size_t)m*256 + ci] = __float2half_rn(v);
    } else {
        cat[(size_t)m*512 + c] = __float2half_rn(v);
    }
}

// ------------------------ selective scan ------------------------
// dbc layout per token: [0..255] dt (softplus'd), [256..271] B, [272..287] C
__global__ void scan_kernel(const float* __restrict__ dbc,
                            const float* __restrict__ xm, const float* __restrict__ A_log,
                            const float* __restrict__ Dp, __half* __restrict__ cat){
    int gid = blockIdx.x*blockDim.x + threadIdx.x;
    int pair = gid >> 4, n = gid & 15;
    int b = pair >> 8, d = pair & 255;
    float A = -expf(A_log[d*16 + n]);
    float Dval = Dp[d];
    float hst = 0.f;
    int base = b*LL;
    for (int l=0;l<LL;l++){
        int m = base + l;
        float dtv = dbc[(size_t)m*384 + d];
        float u   = xm[(size_t)m*256 + d];
        float Bv  = dbc[(size_t)m*384 + 256 + n];
        float Cv  = dbc[(size_t)m*384 + 272 + n];
        hst = expf(dtv*A)*hst + (dtv*u)*Bv;
        float y = hst*Cv;
        #pragma unroll
        for (int off=8;off;off>>=1) y += __shfl_xor_sync(~0u, y, off);
        if (n == 0) cat[(size_t)m*512 + d] = __float2half_rn(y + Dval*u);
    }
}

// ------------------------ attention (flash-style, float4-vectorized smem) ---------
__global__ void __launch_bounds__(224) attn_kernel(const __half* __restrict__ qkv, __half* __restrict__ o){
    extern __shared__ float smem[];
    float* Ks = smem;
    float* Vs = smem + LL*64;
    int bh = blockIdx.x; int b = bh >> 3, h = bh & 7;
    for (int idx = threadIdx.x; idx < LL*64; idx += 224){
        int l = idx >> 6, dd = idx & 63;
        const __half* p = qkv + (size_t)(b*LL + l)*1536 + h*64 + dd;
        Ks[idx] = __half2float(p[512]);
        Vs[idx] = __half2float(p[1024]);
    }
    __syncthreads();
    int l = threadIdx.x;
    if (l < LL){
        float4 q4[16];
        {
            const __half* qp = qkv + (size_t)(b*LL + l)*1536 + h*64;
            #pragma unroll
            for (int i=0;i<16;i++){
                q4[i] = make_float4(__half2float(qp[4*i]),   __half2float(qp[4*i+1]),
                                    __half2float(qp[4*i+2]), __half2float(qp[4*i+3]));
            }
        }
        float4 oa[16];
        #pragma unroll
        for (int i=0;i<16;i++) oa[i] = make_float4(0.f,0.f,0.f,0.f);
        float m = -1e30f, ssum = 0.f;
        for (int jb=0; jb<LL; jb+=14){
            float s[14];
            float mx = m;
            #pragma unroll
            for (int jj=0;jj<14;jj++){
                const float4* kp = (const float4*)(Ks + (jb+jj)*64);
                float acc = 0.f;
                #pragma unroll
                for (int i=0;i<16;i++){
                    float4 kv = kp[i];
                    acc += q4[i].x*kv.x + q4[i].y*kv.y + q4[i].z*kv.z + q4[i].w*kv.w;
                }
                acc *= 0.125f;
                s[jj] = acc;
                mx = fmaxf(mx, acc);
            }
            float scale = expf(m - mx);
            ssum *= scale;
            #pragma unroll
            for (int i=0;i<16;i++){
                oa[i].x *= scale; oa[i].y *= scale; oa[i].z *= scale; oa[i].w *= scale;
            }
            m = mx;
            #pragma unroll
            for (int jj=0;jj<14;jj++){
                float e = expf(s[jj] - m);
                ssum += e;
                const float4* vp = (const float4*)(Vs + (jb+jj)*64);
                #pragma unroll
                for (int i=0;i<16;i++){
                    float4 vv = vp[i];
                    oa[i].x += e*vv.x; oa[i].y += e*vv.y; oa[i].z += e*vv.z; oa[i].w += e*vv.w;
                }
            }
        }
        float inv = 1.f/ssum;
        __half* op = o + (size_t)(b*LL + l)*512 + h*64;
        #pragma unroll
        for (int i=0;i<16;i++){
            op[4*i]   = __float2half_rn(oa[i].x*inv);
            op[4*i+1] = __float2half_rn(oa[i].y*inv);
            op[4*i+2] = __float2half_rn(oa[i].z*inv);
            op[4*i+3] = __float2half_rn(oa[i].w*inv);
        }
    }
}

// ------------------------ mean over L ------------------------
__global__ void pool_kernel(const float* __restrict__ t, float* __restrict__ tmean){
    int idx = blockIdx.x*blockDim.x + threadIdx.x;
    if (idx >= BB*DM) return;
    int b = idx / DM, c = idx % DM;
    const float* p = t + (size_t)b*LL*DM + c;
    float s = 0.f;
    for (int l=0;l<LL;l++) s += p[(size_t)l*DM];
    tmean[idx] = s * (1.f/LL);
}

// ------------------------ final fc ------------------------
__global__ void fc_kernel(const float* __restrict__ pooled, const float* __restrict__ fw,
                          const float* __restrict__ fb, float* __restrict__ out){
    int i = threadIdx.x; // 0..127
    int b = i >> 2, oi = i & 3;
    float s = fb[oi];
    const float* pp = pooled + b*1024;
    const float* wp = fw + oi*1024;
    for (int k=0;k<1024;k++) s += pp[k]*wp[k];
    out[b*4 + oi] = s;
}

// ------------------------ host ------------------------
static void hgemm(const __half* A, int lda, const __half* W, const float* bias,
                  const float* res, int ldres, float* C, __half* Ch, int ldc,
                  int M, int N, int K, int act){
    dim3 grid(N/128, M/128);
    hgemm_kernel<<<grid, 512>>>(A, lda, W, bias, res, ldres, C, Ch, ldc, M, N, K, act);
}

extern "C" void kernel_launch(void* const* d_in, const int* in_sizes, int n_in,
                              void* d_out, int out_size)
{
    const float* x          = (const float*)d_in[0];
    const float* patch_w    = (const float*)d_in[1];
    const float* patch_b    = (const float*)d_in[2];
    const float* ln1_g      = (const float*)d_in[3];
    const float* ln1_b      = (const float*)d_in[4];
    const float* in_proj_w  = (const float*)d_in[5];
    const float* convx_w    = (const float*)d_in[6];
    const float* convx_b    = (const float*)d_in[7];
    const float* convz_w    = (const float*)d_in[8];
    const float* convz_b    = (const float*)d_in[9];
    const float* x_proj_w   = (const float*)d_in[10];
    const float* dt_proj_w  = (const float*)d_in[11];
    const float* dt_proj_b  = (const float*)d_in[12];
    const float* A_log      = (const float*)d_in[13];
    const float* Dp         = (const float*)d_in[14];
    const float* out_proj_w = (const float*)d_in[15];
    const float* ln2_g      = (const float*)d_in[16];
    const float* ln2_b      = (const float*)d_in[17];
    const float* qkv_w      = (const float*)d_in[18];
    const float* attn_proj_w= (const float*)d_in[19];
    const float* ln3_g      = (const float*)d_in[20];
    const float* ln3_b      = (const float*)d_in[21];
    const float* mlp_w1     = (const float*)d_in[22];
    const float* mlp_b1     = (const float*)d_in[23];
    const float* mlp_w2     = (const float*)d_in[24];
    const float* mlp_b2     = (const float*)d_in[25];
    const float* head_w     = (const float*)d_in[26];
    const float* head_b     = (const float*)d_in[27];
    const float* fc_w       = (const float*)d_in[28];
    const float* fc_b       = (const float*)d_in[29];
    float* out = (float*)d_out;

    float *t,*xz,*xm,*dbc,*tmean,*pooled;
    __half *patches,*h,*xm_h,*cat,*qkv,*o,*hid,*wpool;
    cudaGetSymbolAddress((void**)&t,       g_t);
    cudaGetSymbolAddress((void**)&xz,      g_xz);
    cudaGetSymbolAddress((void**)&xm,      g_xm);
    cudaGetSymbolAddress((void**)&dbc,     g_dbc);
    cudaGetSymbolAddress((void**)&tmean,   g_tmean);
    cudaGetSymbolAddress((void**)&pooled,  g_pooled);
    cudaGetSymbolAddress((void**)&patches, g_patches_h);
    cudaGetSymbolAddress((void**)&h,       g_h_h);
    cudaGetSymbolAddress((void**)&xm_h,    g_xm_h);
    cudaGetSymbolAddress((void**)&cat,     g_cat_h);
    cudaGetSymbolAddress((void**)&qkv,     g_qkv_h);
    cudaGetSymbolAddress((void**)&o,       g_o_h);
    cudaGetSymbolAddress((void**)&hid,     g_hid_h);
    cudaGetSymbolAddress((void**)&wpool,   g_wpool_h);

    cudaFuncSetAttribute(attn_kernel, cudaFuncAttributeMaxDynamicSharedMemorySize, 2*LL*64*4);

    // 0. weights -> fp16 pool (one launch) + combined dt/B/C weight
    cvtall_kernel<<<(1015808+255)/256,256>>>(patch_w, in_proj_w, out_proj_w, qkv_w,
                                             attn_proj_w, mlp_w1, mlp_w2, wpool);
    wdt_kernel<<<(98304+255)/256,256>>>(dt_proj_w, x_proj_w, wpool+WOFF_COMB);

    // 1. patch embed
    im2col_kernel<<<(M_TOK*768 + 255)/256, 256>>>(x, patches);
    hgemm(patches, 768, wpool+WOFF_PATCH, patch_b, nullptr, 0, t, nullptr, 512, M_TOK, 512, 768, 0);
    // 2. mamba branch
    ln_kernel<<<M_TOK, 256>>>(t, ln1_g, ln1_b, h);
    hgemm(h, 512, wpool+WOFF_INP, nullptr, nullptr, 0, xz, nullptr, 512, M_TOK, 512, 512, 0);
    conv_silu_kernel<<<(M_TOK*512 + 255)/256, 256>>>(xz, convx_w, convx_b, convz_w, convz_b, xm, xm_h, cat);
    hgemm(xm_h, 256, wpool+WOFF_COMB, dt_proj_b, nullptr, 0, dbc, nullptr, 384, M_TOK, 384, 256, 1);
    scan_kernel<<<512, 256>>>(dbc, xm, A_log, Dp, cat);
    hgemm(cat, 512, wpool+WOFF_OUTP, nullptr, t, 512, t, nullptr, 512, M_TOK, 512, 512, 0);
    // 3. attention
    ln_kernel<<<M_TOK, 256>>>(t, ln2_g, ln2_b, h);
    hgemm(h, 512, wpool+WOFF_QKV, nullptr, nullptr, 0, nullptr, qkv, 1536, M_TOK, 1536, 512, 0);
    attn_kernel<<<BB*8, 224, 2*LL*64*4>>>(qkv, o);
    hgemm(o, 512, wpool+WOFF_ATTNP, nullptr, t, 512, t, nullptr, 512, M_TOK, 512, 512, 0);
    // 4. MLP
    ln_kernel<<<M_TOK, 256>>>(t, ln3_g, ln3_b, h);
    hgemm(h, 512, wpool+WOFF_MLP1, mlp_b1, nullptr, 0, nullptr, hid, 2048, M_TOK, 2048, 512, 2);
    hgemm(hid, 2048, wpool+WOFF_MLP2, mlp_b2, t, 512, t, nullptr, 512, M_TOK, 512, 2048, 0);
    // 5. head (pool first: mean_L(t @ W^T + b) == mean_L(t) @ W^T + b)
    pool_kernel<<<(BB*DM + 255)/256, 256>>>(t, tmean);
    {
        dim3 grid((1024+63)/64, 1);
        sgemm_kernel<<<grid, 256>>>(tmean, 512, head_w, head_b, pooled, 1024, BB, 1024, 512);
    }
    fc_kernel<<<1, 128>>>(pooled, fc_w, fc_b, out);
}

// round 13
// speedup vs baseline: 1.1229x; 1.0799x over previous
#include <cuda_runtime.h>
#include <cuda_fp16.h>
#include <math.h>

#define BB 32
#define LL 196
#define DM 512
#define DI 256
#define M_TOK (BB*LL)   // 6272

// ------------------------ scratch ------------------------
__device__ __align__(16) float  g_t[M_TOK*DM];
__device__ __align__(16) float  g_xz[M_TOK*2*DI];
__device__ __align__(16) float  g_xm[M_TOK*DI];
__device__ __align__(16) float  g_dbc[M_TOK*384];
__device__ __align__(16) float  g_tmean[BB*DM];
__device__ __align__(16) float  g_pooled[BB*1024];
__device__ __align__(16) __half g_patches_h[M_TOK*768];
__device__ __align__(16) __half g_h_h[M_TOK*DM];
__device__ __align__(16) __half g_xm_h[M_TOK*DI];
__device__ __align__(16) __half g_cat_h[M_TOK*2*DI];
__device__ __align__(16) __half g_qkv_h[M_TOK*3*DM];
__device__ __align__(16) __half g_o_h[M_TOK*DM];
__device__ __align__(16) __half g_hid_h[M_TOK*2048];
__device__ __align__(16) __half g_wpool_h[4161536];

// weight pool offsets (elements)
#define WOFF_PATCH 0
#define WOFF_INP   393216
#define WOFF_OUTP  655360
#define WOFF_QKV   917504
#define WOFF_ATTNP 1703936
#define WOFF_MLP1  1966080
#define WOFF_MLP2  3014656
#define WOFF_COMB  4063232   // 384x256 combined dt/B/C projection

// ------------------------ fused weight fp32 -> fp16 (all 7 big weights) ---------
__global__ void cvtall_kernel(const float* __restrict__ pw,  const float* __restrict__ ipw,
                              const float* __restrict__ opw, const float* __restrict__ qw,
                              const float* __restrict__ apw, const float* __restrict__ m1,
                              const float* __restrict__ m2,  __half* __restrict__ dst){
    int i = blockIdx.x*blockDim.x + threadIdx.x;
    if (i >= 1015808) return;
    const float* src; int base;
    if      (i <  98304){ src=pw;  base=0; }
    else if (i < 163840){ src=ipw; base=98304; }
    else if (i < 229376){ src=opw; base=163840; }
    else if (i < 425984){ src=qw;  base=229376; }
    else if (i < 491520){ src=apw; base=425984; }
    else if (i < 753664){ src=m1;  base=491520; }
    else                { src=m2;  base=753664; }
    float4 v = ((const float4*)src)[i-base];
    __half2 h0 = __floats2half2_rn(v.x, v.y);
    __half2 h1 = __floats2half2_rn(v.z, v.w);
    ((uint2*)dst)[i] = make_uint2(*(unsigned*)&h0, *(unsigned*)&h1);
}

// ------------------------ combined dt/B/C weight build ------------------------
__global__ void wdt_kernel(const float* __restrict__ dtw, const float* __restrict__ xpw,
                           __half* __restrict__ comb){
    int idx = blockIdx.x*blockDim.x + threadIdx.x;   // 384*256 = 98304
    if (idx >= 98304) return;
    int n = idx >> 8, k = idx & 255;
    float v = 0.f;
    if (n < 256){
        #pragma unroll
        for (int j=0;j<16;j++) v += dtw[n*16+j]*xpw[j*256+k];
    } else if (n < 288){
        v = xpw[(n-240)*256 + k];
    }
    comb[idx] = __float2half_rn(v);
}

// ------------------------ im2col (half out) ------------------------
__global__ void im2col_kernel(const float* __restrict__ x, __half* __restrict__ out){
    int idx = blockIdx.x*blockDim.x + threadIdx.x;
    if (idx >= M_TOK*768) return;
    int m = idx / 768, k = idx % 768;
    int b = m / LL, l = m % LL;
    int py = l / 14, px = l % 14;
    int c = k / 256, r = k % 256;
    int i = r / 16, j = r % 16;
    out[idx] = __float2half_rn(x[(((size_t)b*3 + c)*224 + py*16 + i)*224 + px*16 + j]);
}

// ------------------------ FP16 tensor-core GEMM (512 thr, cp.async 4-stage) -----
// C[M,N] = A[M,K] @ W[N,K]^T (+bias)(+act)(+res). A, W fp16, accum fp32.
// REQUIRES M%128==0, N%128==0, K%32==0, K/32 >= 3.
// act: 0 none, 1 softplus cols<256 (bias only cols<256), 2 gelu.
// Block 128x128, 16 warps (4m x 4n), warp tile 32x32, mma m16n8k16, ldmatrix.x4,
// 4-stage cp.async pipeline, rows padded to 40 halfs (80B, conflict-free LDSM).
__device__ __forceinline__ void ldm4a(unsigned* r, unsigned addr){
    asm volatile("ldmatrix.sync.aligned.m8n8.x4.shared.b16 {%0,%1,%2,%3}, [%4];"
        : "=r"(r[0]), "=r"(r[1]), "=r"(r[2]), "=r"(r[3]) : "r"(addr));
}
#define HMMA(cacc, a, b0, b1) \
    asm volatile("mma.sync.aligned.m16n8k16.row.col.f32.f16.f16.f32 " \
        "{%0,%1,%2,%3}, {%4,%5,%6,%7}, {%8,%9}, {%0,%1,%2,%3};" \
        : "+f"(cacc[0]), "+f"(cacc[1]), "+f"(cacc[2]), "+f"(cacc[3]) \
        : "r"(a[0]), "r"(a[1]), "r"(a[2]), "r"(a[3]), "r"(b0), "r"(b1))

__device__ __forceinline__ void cp16(unsigned dst, const void* src){
    asm volatile("cp.async.cg.shared.global [%0], [%1], 16;\n" :: "r"(dst), "l"(src));
}
__device__ __forceinline__ void cp_commit(){ asm volatile("cp.async.commit_group;\n" ::); }
template<int N> __device__ __forceinline__ void cp_wait(){
    asm volatile("cp.async.wait_group %0;\n" :: "n"(N));
}

#define TG_STAGES 4
#define STAGE_BYTES 20480u     // 128*40 halfs * 2B * 2 operands
#define HG_SMEM (TG_STAGES*STAGE_BYTES)

__global__ void __launch_bounds__(512,2) hgemm_kernel(
        const __half* __restrict__ A, int lda,
        const __half* __restrict__ W,
        const float* __restrict__ bias,
        const float* __restrict__ res, int ldres,
        float* __restrict__ C, __half* __restrict__ Ch, int ldc,
        int M, int N, int K, int act)
{
    extern __shared__ __align__(16) __half smem_h[];
    unsigned sbase = (unsigned)__cvta_generic_to_shared(smem_h);
    int bm = blockIdx.y*128, bn = blockIdx.x*128;
    int tid = threadIdx.x;
    int warp = tid >> 5, lane = tid & 31;
    int wm = (warp & 3) * 32;
    int wn = (warp >> 2) * 32;
    int gid = lane >> 2, tig = lane & 3;
    int lane15 = lane & 15, laneh = lane >> 4;

    float c[2][4][4];
    #pragma unroll
    for (int mi=0;mi<2;mi++)
        #pragma unroll
        for (int ni=0;ni<4;ni++)
            #pragma unroll
            for (int q=0;q<4;q++) c[mi][ni][q] = 0.f;

    // precomputed LDSM fragment addresses (stage 0; add stage byte offset later)
    unsigned aAddr[2], wAddr[2];
    #pragma unroll
    for (int mi=0;mi<2;mi++)
        aAddr[mi] = sbase + (unsigned)(((wm + mi*16 + lane15)*40 + laneh*8) * 2);
    #pragma unroll
    for (int nip=0;nip<2;nip++)
        wAddr[nip] = sbase + 10240u + (unsigned)(((wn + nip*16 + lane15)*40 + laneh*8) * 2);

    // staging: one cp.async 16B per thread per operand: row = tid>>2, kb = (tid&3)*8
    int srow = tid >> 2;
    int skb  = (tid & 3) * 8;
    unsigned stOff = (unsigned)((srow*40 + skb) * 2);
    const __half* Ag = A + (size_t)(bm+srow)*lda + skb;
    const __half* Wg = W + (size_t)(bn+srow)*K   + skb;

    #define ISSUE(st, k0) { \
        unsigned d = sbase + (unsigned)(st)*STAGE_BYTES + stOff; \
        cp16(d,          Ag + (k0)); \
        cp16(d + 10240u, Wg + (k0)); }

    // compute one 32-K chunk from stage with byte offset boff
    #define COMPUTE(boff) { \
        _Pragma("unroll") \
        for (int kh=0; kh<2; kh++){ \
            unsigned a[2][4], bf[2][4]; \
            ldm4a(a[0],  aAddr[0] + (boff) + kh*32); \
            ldm4a(a[1],  aAddr[1] + (boff) + kh*32); \
            ldm4a(bf[0], wAddr[0] + (boff) + kh*32); \
            ldm4a(bf[1], wAddr[1] + (boff) + kh*32); \
            _Pragma("unroll") \
            for (int mi=0;mi<2;mi++) \
                _Pragma("unroll") \
                for (int nip=0; nip<2; nip++){ \
                    HMMA(c[mi][2*nip],   a[mi], bf[nip][0], bf[nip][2]); \
                    HMMA(c[mi][2*nip+1], a[mi], bf[nip][1], bf[nip][3]); \
                } \
        } }

    const int niter = K >> 5;
    #pragma unroll
    for (int s=0; s<TG_STAGES-1; s++){ ISSUE(s, s*32); cp_commit(); }

    for (int i=0; i<niter; i++){
        cp_wait<TG_STAGES-2>();
        __syncthreads();
        COMPUTE((unsigned)(i & 3)*STAGE_BYTES);
        int nx = i + TG_STAGES - 1;
        if (nx < niter){ ISSUE(nx & 3, nx*32); }
        cp_commit();
    }

    // epilogue
    #pragma unroll
    for (int mi=0;mi<2;mi++){
        #pragma unroll
        for (int ni=0;ni<4;ni++){
            int col = bn + wn + ni*8 + 2*tig;
            #pragma unroll
            for (int half=0; half<2; half++){
                int row = bm + wm + mi*16 + gid + half*8;
                float v0 = c[mi][ni][half*2+0];
                float v1 = c[mi][ni][half*2+1];
                if (bias && (act != 1 || col < 256)){ v0 += bias[col]; v1 += bias[col+1]; }
                if (act == 2){
                    float u = v0, t = tanhf(0.7978845608f*(u + 0.044715f*u*u*u));
                    v0 = 0.5f*u*(1.f + t);
                    u = v1; t = tanhf(0.7978845608f*(u + 0.044715f*u*u*u));
                    v1 = 0.5f*u*(1.f + t);
                } else if (act == 1 && col < 256){
                    v0 = (v0 > 20.f) ? v0 : log1pf(expf(v0));
                    v1 = (v1 > 20.f) ? v1 : log1pf(expf(v1));
                }
                if (res){
                    v0 += res[(size_t)row*ldres + col];
                    v1 += res[(size_t)row*ldres + col+1];
                }
                if (C)  *(float2*)&C[(size_t)row*ldc + col] = make_float2(v0, v1);
                if (Ch) *(__half2*)&Ch[(size_t)row*ldc + col] = __floats2half2_rn(v0, v1);
            }
        }
    }
}

// ------------------------ scalar SGEMM (head: M=32) ------------------------
__global__ void sgemm_kernel(const float* __restrict__ A, int lda,
                             const float* __restrict__ W,
                             const float* __restrict__ bias,
                             float* __restrict__ C, int ldc,
                             int M, int N, int K)
{
    __shared__ float As[16][65];
    __shared__ float Bs[16][65];
    int bm = blockIdx.y*64, bn = blockIdx.x*64;
    int tx = threadIdx.x & 15, ty = threadIdx.x >> 4;
    float acc[4][4];
    #pragma unroll
    for (int i=0;i<4;i++)
        #pragma unroll
        for (int j=0;j<4;j++) acc[i][j]=0.f;

    int lm = threadIdx.x >> 2;
    int lq = (threadIdx.x & 3) * 4;
    int arow = bm + lm;
    int wrow = bn + lm;

    for (int k0=0;k0<K;k0+=16){
        float4 av = make_float4(0.f,0.f,0.f,0.f);
        float4 wv = make_float4(0.f,0.f,0.f,0.f);
        if (arow < M) av = *(const float4*)&A[(size_t)arow*lda + k0 + lq];
        if (wrow < N) wv = *(const float4*)&W[(size_t)wrow*K   + k0 + lq];
        As[lq+0][lm]=av.x; As[lq+1][lm]=av.y; As[lq+2][lm]=av.z; As[lq+3][lm]=av.w;
        Bs[lq+0][lm]=wv.x; Bs[lq+1][lm]=wv.y; Bs[lq+2][lm]=wv.z; Bs[lq+3][lm]=wv.w;
        __syncthreads();
        #pragma unroll
        for (int kk=0;kk<16;kk++){
            float a[4], bv[4];
            #pragma unroll
            for (int i=0;i<4;i++) a[i] = As[kk][ty + 16*i];
            #pragma unroll
            for (int j=0;j<4;j++) bv[j] = Bs[kk][tx + 16*j];
            #pragma unroll
            for (int i=0;i<4;i++)
                #pragma unroll
                for (int j=0;j<4;j++) acc[i][j] += a[i]*bv[j];
        }
        __syncthreads();
    }
    #pragma unroll
    for (int i=0;i<4;i++){
        int row = bm + ty + 16*i;
        if (row >= M) continue;
        #pragma unroll
        for (int j=0;j<4;j++){
            int col = bn + tx + 16*j;
            if (col >= N) continue;
            float v = acc[i][j];
            if (bias) v += bias[col];
            C[(size_t)row*ldc + col] = v;
        }
    }
}

// ------------------------ LayerNorm (half out) ------------------------
__global__ void ln_kernel(const float* __restrict__ x, const float* __restrict__ g,
                          const float* __restrict__ be, __half* __restrict__ y){
    int m = blockIdx.x;
    const float* row = x + (size_t)m*DM;
    float s = 0.f, ss = 0.f;
    for (int c = threadIdx.x; c < DM; c += 256){ float v = row[c]; s += v; ss += v*v; }
    #pragma unroll
    for (int off=16;off;off>>=1){ s += __shfl_xor_sync(~0u,s,off); ss += __shfl_xor_sync(~0u,ss,off); }
    __shared__ float sh[16];
    __shared__ float stat[2];
    int wid = threadIdx.x >> 5, lid = threadIdx.x & 31;
    if (lid == 0){ sh[wid] = s; sh[wid+8] = ss; }
    __syncthreads();
    if (threadIdx.x == 0){
        float ts=0.f, tss=0.f;
        for (int w=0;w<8;w++){ ts += sh[w]; tss += sh[w+8]; }
        float mean = ts * (1.f/DM);
        float var  = tss * (1.f/DM) - mean*mean;
        stat[0] = mean;
        stat[1] = rsqrtf(var + 1e-6f);
    }
    __syncthreads();
    float mean = stat[0], rstd = stat[1];
    for (int c = threadIdx.x; c < DM; c += 256){
        y[(size_t)m*DM + c] = __float2half_rn((row[c] - mean)*rstd*g[c] + be[c]);
    }
}

// ------------------------ causal depthwise conv (k=4) + SiLU ------------------------
__global__ void conv_silu_kernel(const float* __restrict__ xz,
                                 const float* __restrict__ wx, const float* __restrict__ bx,
                                 const float* __restrict__ wz, const float* __restrict__ bz,
                                 float* __restrict__ xm, __half* __restrict__ xm_h,
                                 __half* __restrict__ cat){
    int idx = blockIdx.x*blockDim.x + threadIdx.x;
    if (idx >= M_TOK*512) return;
    int m = idx >> 9, c = idx & 511;
    int b = m / LL, l = m % LL;
    bool isx = (c < 256);
    int ci = isx ? c : c - 256;
    const float* w = isx ? (wx + ci*4) : (wz + ci*4);
    float s = isx ? bx[ci] : bz[ci];
    #pragma unroll
    for (int k=0;k<4;k++){
        int ls = l - 3 + k;
        if (ls >= 0) s += w[k] * xz[((size_t)(b*LL + ls))*512 + c];
    }
    float v = s / (1.f + expf(-s));   // silu
    if (isx){
        xm[(size_t)m*256 + ci] = v;
        xm_h[(size_t)m*256 + ci] = __float2half_rn(v);
    } else {
        cat[(size_t)m*512 + c] = __float2half_rn(v);
    }
}

// ------------------------ selective scan ------------------------
// dbc layout per token: [0..255] dt (softplus'd), [256..271] B, [272..287] C
__global__ void scan_kernel(const float* __restrict__ dbc,
                            const float* __restrict__ xm, const float* __restrict__ A_log,
                            const float* __restrict__ Dp, __half* __restrict__ cat){
    int gid = blockIdx.x*blockDim.x + threadIdx.x;
    int pair = gid >> 4, n = gid & 15;
    int b = pair >> 8, d = pair & 255;
    float A = -expf(A_log[d*16 + n]);
    float Dval = Dp[d];
    float hst = 0.f;
    int base = b*LL;
    for (int l=0;l<LL;l++){
        int m = base + l;
        float dtv = dbc[(size_t)m*384 + d];
        float u   = xm[(size_t)m*256 + d];
        float Bv  = dbc[(size_t)m*384 + 256 + n];
        float Cv  = dbc[(size_t)m*384 + 272 + n];
        hst = expf(dtv*A)*hst + (dtv*u)*Bv;
        float y = hst*Cv;
        #pragma unroll
        for (int off=8;off;off>>=1) y += __shfl_xor_sync(~0u, y, off);
        if (n == 0) cat[(size_t)m*512 + d] = __float2half_rn(y + Dval*u);
    }
}

// ------------------------ attention (flash-style, float4-vectorized smem) ---------
__global__ void __launch_bounds__(224) attn_kernel(const __half* __restrict__ qkv, __half* __restrict__ o){
    extern __shared__ float smem[];
    float* Ks = smem;
    float* Vs = smem + LL*64;
    int bh = blockIdx.x; int b = bh >> 3, h = bh & 7;
    for (int idx = threadIdx.x; idx < LL*64; idx += 224){
        int l = idx >> 6, dd = idx & 63;
        const __half* p = qkv + (size_t)(b*LL + l)*1536 + h*64 + dd;
        Ks[idx] = __half2float(p[512]);
        Vs[idx] = __half2float(p[1024]);
    }
    __syncthreads();
    int l = threadIdx.x;
    if (l < LL){
        float4 q4[16];
        {
            const __half* qp = qkv + (size_t)(b*LL + l)*1536 + h*64;
            #pragma unroll
            for (int i=0;i<16;i++){
                q4[i] = make_float4(__half2float(qp[4*i]),   __half2float(qp[4*i+1]),
                                    __half2float(qp[4*i+2]), __half2float(qp[4*i+3]));
            }
        }
        float4 oa[16];
        #pragma unroll
        for (int i=0;i<16;i++) oa[i] = make_float4(0.f,0.f,0.f,0.f);
        float m = -1e30f, ssum = 0.f;
        for (int jb=0; jb<LL; jb+=14){
            float s[14];
            float mx = m;
            #pragma unroll
            for (int jj=0;jj<14;jj++){
                const float4* kp = (const float4*)(Ks + (jb+jj)*64);
                float acc = 0.f;
                #pragma unroll
                for (int i=0;i<16;i++){
                    float4 kv = kp[i];
                    acc += q4[i].x*kv.x + q4[i].y*kv.y + q4[i].z*kv.z + q4[i].w*kv.w;
                }
                acc *= 0.125f;
                s[jj] = acc;
                mx = fmaxf(mx, acc);
            }
            float scale = expf(m - mx);
            ssum *= scale;
            #pragma unroll
            for (int i=0;i<16;i++){
                oa[i].x *= scale; oa[i].y *= scale; oa[i].z *= scale; oa[i].w *= scale;
            }
            m = mx;
            #pragma unroll
            for (int jj=0;jj<14;jj++){
                float e = expf(s[jj] - m);
                ssum += e;
                const float4* vp = (const float4*)(Vs + (jb+jj)*64);
                #pragma unroll
                for (int i=0;i<16;i++){
                    float4 vv = vp[i];
                    oa[i].x += e*vv.x; oa[i].y += e*vv.y; oa[i].z += e*vv.z; oa[i].w += e*vv.w;
                }
            }
        }
        float inv = 1.f/ssum;
        __half* op = o + (size_t)(b*LL + l)*512 + h*64;
        #pragma unroll
        for (int i=0;i<16;i++){
            op[4*i]   = __float2half_rn(oa[i].x*inv);
            op[4*i+1] = __float2half_rn(oa[i].y*inv);
            op[4*i+2] = __float2half_rn(oa[i].z*inv);
            op[4*i+3] = __float2half_rn(oa[i].w*inv);
        }
    }
}

// ------------------------ mean over L ------------------------
__global__ void pool_kernel(const float* __restrict__ t, float* __restrict__ tmean){
    int idx = blockIdx.x*blockDim.x + threadIdx.x;
    if (idx >= BB*DM) return;
    int b = idx / DM, c = idx % DM;
    const float* p = t + (size_t)b*LL*DM + c;
    float s = 0.f;
    for (int l=0;l<LL;l++) s += p[(size_t)l*DM];
    tmean[idx] = s * (1.f/LL);
}

// ------------------------ final fc ------------------------
__global__ void fc_kernel(const float* __restrict__ pooled, const float* __restrict__ fw,
                          const float* __restrict__ fb, float* __restrict__ out){
    int i = threadIdx.x; // 0..127
    int b = i >> 2, oi = i & 3;
    float s = fb[oi];
    const float* pp = pooled + b*1024;
    const float* wp = fw + oi*1024;
    for (int k=0;k<1024;k++) s += pp[k]*wp[k];
    out[b*4 + oi] = s;
}

// ------------------------ host ------------------------
static void hgemm(const __half* A, int lda, const __half* W, const float* bias,
                  const float* res, int ldres, float* C, __half* Ch, int ldc,
                  int M, int N, int K, int act){
    dim3 grid(N/128, M/128);
    hgemm_kernel<<<grid, 512, HG_SMEM>>>(A, lda, W, bias, res, ldres, C, Ch, ldc, M, N, K, act);
}

extern "C" void kernel_launch(void* const* d_in, const int* in_sizes, int n_in,
                              void* d_out, int out_size)
{
    const float* x          = (const float*)d_in[0];
    const float* patch_w    = (const float*)d_in[1];
    const float* patch_b    = (const float*)d_in[2];
    const float* ln1_g      = (const float*)d_in[3];
    const float* ln1_b      = (const float*)d_in[4];
    const float* in_proj_w  = (const float*)d_in[5];
    const float* convx_w    = (const float*)d_in[6];
    const float* convx_b    = (const float*)d_in[7];
    const float* convz_w    = (const float*)d_in[8];
    const float* convz_b    = (const float*)d_in[9];
    const float* x_proj_w   = (const float*)d_in[10];
    const float* dt_proj_w  = (const float*)d_in[11];
    const float* dt_proj_b  = (const float*)d_in[12];
    const float* A_log      = (const float*)d_in[13];
    const float* Dp         = (const float*)d_in[14];
    const float* out_proj_w = (const float*)d_in[15];
    const float* ln2_g      = (const float*)d_in[16];
    const float* ln2_b      = (const float*)d_in[17];
    const float* qkv_w      = (const float*)d_in[18];
    const float* attn_proj_w= (const float*)d_in[19];
    const float* ln3_g      = (const float*)d_in[20];
    const float* ln3_b      = (const float*)d_in[21];
    const float* mlp_w1     = (const float*)d_in[22];
    const float* mlp_b1     = (const float*)d_in[23];
    const float* mlp_w2     = (const float*)d_in[24];
    const float* mlp_b2     = (const float*)d_in[25];
    const float* head_w     = (const float*)d_in[26];
    const float* head_b     = (const float*)d_in[27];
    const float* fc_w       = (const float*)d_in[28];
    const float* fc_b       = (const float*)d_in[29];
    float* out = (float*)d_out;

    float *t,*xz,*xm,*dbc,*tmean,*pooled;
    __half *patches,*h,*xm_h,*cat,*qkv,*o,*hid,*wpool;
    cudaGetSymbolAddress((void**)&t,       g_t);
    cudaGetSymbolAddress((void**)&xz,      g_xz);
    cudaGetSymbolAddress((void**)&xm,      g_xm);
    cudaGetSymbolAddress((void**)&dbc,     g_dbc);
    cudaGetSymbolAddress((void**)&tmean,   g_tmean);
    cudaGetSymbolAddress((void**)&pooled,  g_pooled);
    cudaGetSymbolAddress((void**)&patches, g_patches_h);
    cudaGetSymbolAddress((void**)&h,       g_h_h);
    cudaGetSymbolAddress((void**)&xm_h,    g_xm_h);
    cudaGetSymbolAddress((void**)&cat,     g_cat_h);
    cudaGetSymbolAddress((void**)&qkv,     g_qkv_h);
    cudaGetSymbolAddress((void**)&o,       g_o_h);
    cudaGetSymbolAddress((void**)&hid,     g_hid_h);
    cudaGetSymbolAddress((void**)&wpool,   g_wpool_h);

    cudaFuncSetAttribute(attn_kernel,  cudaFuncAttributeMaxDynamicSharedMemorySize, 2*LL*64*4);
    cudaFuncSetAttribute(hgemm_kernel, cudaFuncAttributeMaxDynamicSharedMemorySize, HG_SMEM);

    // 0. weights -> fp16 pool (one launch) + combined dt/B/C weight
    cvtall_kernel<<<(1015808+255)/256,256>>>(patch_w, in_proj_w, out_proj_w, qkv_w,
                                             attn_proj_w, mlp_w1, mlp_w2, wpool);
    wdt_kernel<<<(98304+255)/256,256>>>(dt_proj_w, x_proj_w, wpool+WOFF_COMB);

    // 1. patch embed
    im2col_kernel<<<(M_TOK*768 + 255)/256, 256>>>(x, patches);
    hgemm(patches, 768, wpool+WOFF_PATCH, patch_b, nullptr, 0, t, nullptr, 512, M_TOK, 512, 768, 0);
    // 2. mamba branch
    ln_kernel<<<M_TOK, 256>>>(t, ln1_g, ln1_b, h);
    hgemm(h, 512, wpool+WOFF_INP, nullptr, nullptr, 0, xz, nullptr, 512, M_TOK, 512, 512, 0);
    conv_silu_kernel<<<(M_TOK*512 + 255)/256, 256>>>(xz, convx_w, convx_b, convz_w, convz_b, xm, xm_h, cat);
    hgemm(xm_h, 256, wpool+WOFF_COMB, dt_proj_b, nullptr, 0, dbc, nullptr, 384, M_TOK, 384, 256, 1);
    scan_kernel<<<512, 256>>>(dbc, xm, A_log, Dp, cat);
    hgemm(cat, 512, wpool+WOFF_OUTP, nullptr, t, 512, t, nullptr, 512, M_TOK, 512, 512, 0);
    // 3. attention
    ln_kernel<<<M_TOK, 256>>>(t, ln2_g, ln2_b, h);
    hgemm(h, 512, wpool+WOFF_QKV, nullptr, nullptr, 0, nullptr, qkv, 1536, M_TOK, 1536, 512, 0);
    attn_kernel<<<BB*8, 224, 2*LL*64*4>>>(qkv, o);
    hgemm(o, 512, wpool+WOFF_ATTNP, nullptr, t, 512, t, nullptr, 512, M_TOK, 512, 512, 0);
    // 4. MLP
    ln_kernel<<<M_TOK, 256>>>(t, ln3_g, ln3_b, h);
    hgemm(h, 512, wpool+WOFF_MLP1, mlp_b1, nullptr, 0, nullptr, hid, 2048, M_TOK, 2048, 512, 2);
    hgemm(hid, 2048, wpool+WOFF_MLP2, mlp_b2, t, 512, t, nullptr, 512, M_TOK, 512, 2048, 0);
    // 5. head (pool first: mean_L(t @ W^T + b) == mean_L(t) @ W^T + b)
    pool_kernel<<<(BB*DM + 255)/256, 256>>>(t, tmean);
    {
        dim3 grid((1024+63)/64, 1);
        sgemm_kernel<<<grid, 256>>>(tmean, 512, head_w, head_b, pooled, 1024, BB, 1024, 512);
    }
    fc_kernel<<<1, 128>>>(pooled, fc_w, fc_b, out);
}